// round 12
// baseline (speedup 1.0000x reference)
#include <cuda_runtime.h>
#include <cuda_fp16.h>
#include <cstdint>
#include <math.h>

#define NN      100000
#define NEDGE   1600000
#define F       128
#define BQ      8192
#define NSDIM   64
#define NC      16
#define SCAN_NB ((NN + 1023) / 1024)   // 98

// ---------------- scratch (__device__ globals, allocation-free) ----------------
__device__ __half g_bufA[(size_t)NN * F];
__device__ __half g_bufB[(size_t)NN * F];
__device__ __half g_Wh[2][F * F];      // W1,W2 transposed [n][k], fp16

struct CsrScratch {              // zeroed with ONE memset per launch
    int cnt[NN];                 // edge histogram
    int iflag[NN];               // node is in index set
    int flag[NN];                // node is in C* (needed by final)
    int bsum[128];               // csr scan block sums
    int lsum[128];               // list scan block sums
    unsigned int ctr;            // csr scan barrier
    unsigned int lctr;           // list scan barrier
    unsigned int pad[2];
};
__device__ CsrScratch g_cs;
__device__ int   g_ptr[NN + 1];
__device__ int   g_woff[NN];
__device__ int   g_pcol[NEDGE];
__device__ float g_pval[NEDGE];
__device__ int   g_list[NN];     // compacted C* rows
__device__ int   g_nlist;        // |C*|

// fp16 GEMM smem: As2 [128 m][68] half2-as-u32, Ws2 [128 n][68] half2-as-u32
#define S2 68
#define GEMM_SMEM (2 * 128 * S2 * 4)   // 69632 B -> 2 blocks/SM

// ---------------- W transpose+convert: W[k][n] fp32 -> g_Wh[w][n][k] fp16 ----------------
__global__ void wtrans_kernel(const float* __restrict__ W1, const float* __restrict__ W2)
{
    int idx = blockIdx.x * blockDim.x + threadIdx.x;   // 32768 total
    int w   = idx >> 14;
    int rem = idx & 16383;
    int k   = rem >> 7;
    int n   = rem & 127;
    const float* Wsrc = (w == 0) ? W1 : W2;
    g_Wh[w][n * F + k] = __float2half_rn(Wsrc[k * F + n]);
}

// ---------------- fp16 tensor-core GEMM: C[M,128](fp16) = transform(X) @ W ----------------
// FUSE=false: X fp32.  FUSE=true: X fp16, relu(x + bias).
// LIST=true: rows indirected through g_list[0..g_nlist).
template <bool FUSE, bool LIST>
__global__ void gemm128_fp16(const void* __restrict__ Xv, const __half* __restrict__ Wh,
                             const float* __restrict__ bias, __half* __restrict__ C, int M)
{
    extern __shared__ unsigned int smu[];
    unsigned int* As2 = smu;             // [128][S2]  rows m, half2 along k
    unsigned int* Ws2 = smu + 128 * S2;  // [128][S2]  rows n, half2 along k

    const int tid  = threadIdx.x;          // 256 threads, 8 warps
    const int wid  = tid >> 5;
    const int lane = tid & 31;
    const int gid  = lane >> 2;            // 0..7
    const int tig  = lane & 3;             // 0..3
    const int wm   = wid & 3;              // 4 warps over M (32 rows each)
    const int wn   = wid >> 2;             // 2 warps over N (64 cols each)
    const int m0   = blockIdx.x * 128;

    const int nl = LIST ? g_nlist : M;
    if (LIST && m0 >= nl) return;

    // W fp16 [n][k] -> Ws2: 2048 uint4 / 256 thr = 8 vec iters
    #pragma unroll
    for (int i = 0; i < 8; i++) {
        int idx = i * 256 + tid;
        int n = idx >> 4;
        int j = idx & 15;
        uint4 u = ((const uint4*)Wh)[idx];
        *(uint4*)(Ws2 + n * S2 + j * 4) = u;
    }

    // X tile -> As2[m][k/2] half2
    if (FUSE) {
        const __half* Xh = (const __half*)Xv;
        #pragma unroll
        for (int i = 0; i < 8; i++) {
            int idx = i * 256 + tid;        // 2048 chunks of 8 halves
            int m  = idx >> 4;
            int k8 = (idx & 15) << 3;
            int gm = m0 + m;
            bool valid = gm < nl;
            int src = (LIST && valid) ? g_list[gm] : gm;
            uint4 raw = make_uint4(0u, 0u, 0u, 0u);
            if (valid) raw = *(const uint4*)(Xh + (size_t)src * F + k8);
            const __half2* hp = (const __half2*)&raw;
            unsigned int o[4];
            #pragma unroll
            for (int j = 0; j < 4; j++) {
                float2 f = __half22float2(hp[j]);
                float2 bb = *(const float2*)(bias + k8 + j * 2);
                f.x = fmaxf(f.x + bb.x, 0.f);
                f.y = fmaxf(f.y + bb.y, 0.f);
                __half2 h = __floats2half2_rn(f.x, f.y);
                o[j] = *(unsigned int*)&h;
            }
            int base = m * S2 + (k8 >> 1);
            *(uint2*)(As2 + base)     = make_uint2(o[0], o[1]);
            *(uint2*)(As2 + base + 2) = make_uint2(o[2], o[3]);
        }
    } else {
        const float* Xf = (const float*)Xv;
        #pragma unroll
        for (int i = 0; i < 16; i++) {
            int idx = i * 256 + tid;        // 4096 float4
            int m  = idx >> 5;
            int k4 = (idx & 31) << 2;
            int gm = m0 + m;
            float4 v = make_float4(0.f, 0.f, 0.f, 0.f);
            if (gm < nl) v = *(const float4*)(Xf + (size_t)gm * F + k4);
            __half2 h0 = __floats2half2_rn(v.x, v.y);
            __half2 h1 = __floats2half2_rn(v.z, v.w);
            int base = m * S2 + (k4 >> 1);
            *(uint2*)(As2 + base) = make_uint2(*(unsigned int*)&h0, *(unsigned int*)&h1);
        }
    }
    __syncthreads();

    float acc[2][8][4];
    #pragma unroll
    for (int a = 0; a < 2; a++)
        #pragma unroll
        for (int b = 0; b < 8; b++)
            #pragma unroll
            for (int c = 0; c < 4; c++) acc[a][b][c] = 0.f;

    // 8 k-steps of 16
    #pragma unroll
    for (int ks = 0; ks < 8; ks++) {
        const int k0h = ks * 8;
        unsigned int afr[2][4];
        #pragma unroll
        for (int mf = 0; mf < 2; mf++) {
            int rb = wm * 32 + mf * 16 + gid;
            afr[mf][0] = As2[rb * S2 + k0h + tig];
            afr[mf][1] = As2[(rb + 8) * S2 + k0h + tig];
            afr[mf][2] = As2[rb * S2 + k0h + 4 + tig];
            afr[mf][3] = As2[(rb + 8) * S2 + k0h + 4 + tig];
        }
        unsigned int bfr[8][2];
        #pragma unroll
        for (int nf = 0; nf < 8; nf++) {
            int nb = wn * 64 + nf * 8 + gid;
            bfr[nf][0] = Ws2[nb * S2 + k0h + tig];
            bfr[nf][1] = Ws2[nb * S2 + k0h + 4 + tig];
        }
        #pragma unroll
        for (int mf = 0; mf < 2; mf++)
            #pragma unroll
            for (int nf = 0; nf < 8; nf++) {
                asm volatile(
                    "mma.sync.aligned.m16n8k16.row.col.f32.f16.f16.f32 "
                    "{%0,%1,%2,%3}, {%4,%5,%6,%7}, {%8,%9}, {%0,%1,%2,%3};"
                    : "+f"(acc[mf][nf][0]), "+f"(acc[mf][nf][1]),
                      "+f"(acc[mf][nf][2]), "+f"(acc[mf][nf][3])
                    : "r"(afr[mf][0]), "r"(afr[mf][1]), "r"(afr[mf][2]), "r"(afr[mf][3]),
                      "r"(bfr[nf][0]), "r"(bfr[nf][1]));
            }
    }

    #pragma unroll
    for (int mf = 0; mf < 2; mf++) {
        int r0 = m0 + wm * 32 + mf * 16 + gid;
        bool v0 = r0 < nl;
        bool v1 = r0 + 8 < nl;
        int d0 = (LIST && v0) ? g_list[r0] : r0;
        int d1 = (LIST && v1) ? g_list[r0 + 8] : r0 + 8;
        #pragma unroll
        for (int nf = 0; nf < 8; nf++) {
            int ccol = wn * 64 + nf * 8 + tig * 2;
            if (v0)
                *(__half2*)(C + (size_t)d0 * F + ccol) =
                    __floats2half2_rn(acc[mf][nf][0], acc[mf][nf][1]);
            if (v1)
                *(__half2*)(C + (size_t)d1 * F + ccol) =
                    __floats2half2_rn(acc[mf][nf][2], acc[mf][nf][3]);
        }
    }
}

// ---------------- CSR + C* build kernels ----------------
__global__ void flagidx_kernel(const int* __restrict__ index)
{
    int b = blockIdx.x * blockDim.x + threadIdx.x;
    if (b < BQ) g_cs.iflag[index[b]] = 1;
}

__global__ void hist_kernel(const int* __restrict__ row, int ne)
{
    int e = blockIdx.x * blockDim.x + threadIdx.x;
    if (e < ne) atomicAdd(&g_cs.cnt[row[e]], 1);
}

__global__ void mark_kernel(const int* __restrict__ row, const int* __restrict__ col, int ne)
{
    int e = blockIdx.x * blockDim.x + threadIdx.x;
    if (e < ne && g_cs.iflag[row[e]]) g_cs.flag[col[e]] = 1;
}

// exclusive scan of cnt -> g_ptr/g_woff (software grid barrier via ctr/bsum)
__global__ void scan_fused(int n, int ne)
{
    __shared__ int sm[256];
    __shared__ int wsum[8];
    __shared__ int s_prefix;
    const int tid = threadIdx.x;
    const int bid = blockIdx.x;
    const int nb  = gridDim.x;

    int base = bid * 1024 + tid * 4;
    int v[4];
    #pragma unroll
    for (int i = 0; i < 4; i++)
        v[i] = (base + i < n) ? g_cs.cnt[base + i] : 0;
    int tsum = v[0] + v[1] + v[2] + v[3];
    sm[tid] = tsum;
    __syncthreads();
    #pragma unroll
    for (int o = 1; o < 256; o <<= 1) {
        int t = (tid >= o) ? sm[tid - o] : 0;
        __syncthreads();
        sm[tid] += t;
        __syncthreads();
    }

    if (tid == 0) {
        ((volatile int*)g_cs.bsum)[bid] = sm[255];
        __threadfence();
        atomicAdd(&g_cs.ctr, 1u);
        while (((volatile unsigned int*)&g_cs.ctr)[0] < (unsigned)nb) {}
        __threadfence();
    }
    __syncthreads();

    int p = (tid < bid) ? ((volatile int*)g_cs.bsum)[tid] : 0;
    #pragma unroll
    for (int o = 16; o; o >>= 1) p += __shfl_xor_sync(0xffffffffu, p, o);
    if ((tid & 31) == 0) wsum[tid >> 5] = p;
    __syncthreads();
    if (tid < 8) {
        int q = wsum[tid];
        #pragma unroll
        for (int o = 4; o; o >>= 1) q += __shfl_xor_sync(0xffu, q, o);
        if (tid == 0) s_prefix = q;
    }
    __syncthreads();

    int run = s_prefix + sm[tid] - tsum;
    #pragma unroll
    for (int i = 0; i < 4; i++) {
        if (base + i < n) { g_ptr[base + i] = run; g_woff[base + i] = run; }
        run += v[i];
    }
    if (bid == nb - 1 && tid == 0) g_ptr[n] = ne;
}

// compaction scan of flag -> g_list, g_nlist (separate barrier lctr/lsum)
__global__ void compact_kernel(int n)
{
    __shared__ int sm[256];
    __shared__ int wsum[8];
    __shared__ int s_prefix;
    const int tid = threadIdx.x;
    const int bid = blockIdx.x;
    const int nb  = gridDim.x;

    int base = bid * 1024 + tid * 4;
    int v[4];
    #pragma unroll
    for (int i = 0; i < 4; i++)
        v[i] = (base + i < n) ? g_cs.flag[base + i] : 0;
    int tsum = v[0] + v[1] + v[2] + v[3];
    sm[tid] = tsum;
    __syncthreads();
    #pragma unroll
    for (int o = 1; o < 256; o <<= 1) {
        int t = (tid >= o) ? sm[tid - o] : 0;
        __syncthreads();
        sm[tid] += t;
        __syncthreads();
    }

    if (tid == 0) {
        ((volatile int*)g_cs.lsum)[bid] = sm[255];
        __threadfence();
        atomicAdd(&g_cs.lctr, 1u);
        while (((volatile unsigned int*)&g_cs.lctr)[0] < (unsigned)nb) {}
        __threadfence();
    }
    __syncthreads();

    int p = (tid < bid) ? ((volatile int*)g_cs.lsum)[tid] : 0;
    #pragma unroll
    for (int o = 16; o; o >>= 1) p += __shfl_xor_sync(0xffffffffu, p, o);
    if ((tid & 31) == 0) wsum[tid >> 5] = p;
    __syncthreads();
    if (tid < 8) {
        int q = wsum[tid];
        #pragma unroll
        for (int o = 4; o; o >>= 1) q += __shfl_xor_sync(0xffu, q, o);
        if (tid == 0) s_prefix = q;
    }
    __syncthreads();

    int run = s_prefix + sm[tid] - tsum;
    #pragma unroll
    for (int i = 0; i < 4; i++) {
        if (base + i < n && v[i]) g_list[run] = base + i;
        run += v[i];
    }
    if (bid == nb - 1 && tid == 255) g_nlist = run;
}

__global__ void scatter_kernel(const int* __restrict__ row, const int* __restrict__ col,
                               const float* __restrict__ val, int ne)
{
    int e = blockIdx.x * blockDim.x + threadIdx.x;
    if (e < ne) {
        int r = row[e];
        int p = atomicAdd(&g_woff[r], 1);
        g_pcol[p] = col[e];
        g_pval[p] = val[e];
    }
}

// ---------------- SPMM1 over compacted C* rows ----------------
__global__ void __launch_bounds__(256, 6)
spmm_csr(const __half* __restrict__ H, __half* __restrict__ out)
{
    const int tid  = threadIdx.x;     // 256 thr = 16 list entries/block
    const int warp = tid >> 5;
    const int lane = tid & 31;
    const int half = lane >> 4;
    const int hl   = lane & 15;
    int li = blockIdx.x * 16 + warp * 2 + half;
    if (li >= g_nlist) return;
    int r = g_list[li];

    int e0 = g_ptr[r];
    int e1 = g_ptr[r + 1];

    float acc[8] = {0.f, 0.f, 0.f, 0.f, 0.f, 0.f, 0.f, 0.f};
    const size_t off = (size_t)hl * 8;

    int e = e0;
    for (; e + 4 <= e1; e += 4) {
        int   c0 = g_pcol[e],     c1 = g_pcol[e + 1], c2 = g_pcol[e + 2], c3 = g_pcol[e + 3];
        float v0 = g_pval[e],     v1 = g_pval[e + 1], v2 = g_pval[e + 2], v3 = g_pval[e + 3];
        __half2 w0 = __float2half2_rn(v0);
        __half2 w1 = __float2half2_rn(v1);
        __half2 w2 = __float2half2_rn(v2);
        __half2 w3 = __float2half2_rn(v3);
        uint4 r0 = *(const uint4*)(H + (size_t)c0 * F + off);
        uint4 r1 = *(const uint4*)(H + (size_t)c1 * F + off);
        uint4 r2 = *(const uint4*)(H + (size_t)c2 * F + off);
        uint4 r3 = *(const uint4*)(H + (size_t)c3 * F + off);
        const __half2* h0 = (const __half2*)&r0;
        const __half2* h1 = (const __half2*)&r1;
        const __half2* h2 = (const __half2*)&r2;
        const __half2* h3 = (const __half2*)&r3;
        #pragma unroll
        for (int j = 0; j < 4; j++) {
            __half2 hacc = __hmul2(w0, h0[j]);
            hacc = __hfma2(w1, h1[j], hacc);
            hacc = __hfma2(w2, h2[j], hacc);
            hacc = __hfma2(w3, h3[j], hacc);
            float2 f = __half22float2(hacc);
            acc[j*2]   += f.x;
            acc[j*2+1] += f.y;
        }
    }
    for (; e < e1; e++) {
        int c = g_pcol[e];
        float v = g_pval[e];
        uint4 rr = *(const uint4*)(H + (size_t)c * F + off);
        const __half2* hh = (const __half2*)&rr;
        #pragma unroll
        for (int j = 0; j < 4; j++) {
            float2 f = __half22float2(hh[j]);
            acc[j*2]   += v * f.x;
            acc[j*2+1] += v * f.y;
        }
    }
    uint4 o;
    __half2* op = (__half2*)&o;
    #pragma unroll
    for (int j = 0; j < 4; j++)
        op[j] = __floats2half2_rn(acc[j*2], acc[j*2+1]);
    *(uint4*)(out + (size_t)r * F + off) = o;
}

// ---------------- fused: row-restricted SPMM2 + linear + log_softmax ----------------
__global__ void __launch_bounds__(256, 6)
spmm2_final(const __half* __restrict__ H2, const float* __restrict__ b2,
            const float* __restrict__ s, const int* __restrict__ index,
            const float* __restrict__ Wl, const float* __restrict__ bl,
            float* __restrict__ out)
{
    __shared__ float Wls[(F + NSDIM) * NC];
    __shared__ float bls[NC];
    __shared__ float sin[16][F + NSDIM];

    for (int i = threadIdx.x; i < (F + NSDIM) * NC; i += blockDim.x) Wls[i] = Wl[i];
    if (threadIdx.x < NC) bls[threadIdx.x] = bl[threadIdx.x];
    __syncthreads();

    const int tid  = threadIdx.x;
    const int warp = tid >> 5;
    const int lane = tid & 31;
    const int half = lane >> 4;
    const int hl   = lane & 15;
    const int sidx = warp * 2 + half;
    int b = blockIdx.x * 16 + sidx;
    if (b >= BQ) return;

    int r = __ldg(index + b);
    int e0 = g_ptr[r];
    int e1 = g_ptr[r + 1];

    float acc[8] = {0.f, 0.f, 0.f, 0.f, 0.f, 0.f, 0.f, 0.f};
    const size_t off = (size_t)hl * 8;

    int e = e0;
    for (; e + 4 <= e1; e += 4) {
        int   c0 = g_pcol[e],     c1 = g_pcol[e + 1], c2 = g_pcol[e + 2], c3 = g_pcol[e + 3];
        float v0 = g_pval[e],     v1 = g_pval[e + 1], v2 = g_pval[e + 2], v3 = g_pval[e + 3];
        __half2 w0 = __float2half2_rn(v0);
        __half2 w1 = __float2half2_rn(v1);
        __half2 w2 = __float2half2_rn(v2);
        __half2 w3 = __float2half2_rn(v3);
        uint4 r0 = *(const uint4*)(H2 + (size_t)c0 * F + off);
        uint4 r1 = *(const uint4*)(H2 + (size_t)c1 * F + off);
        uint4 r2 = *(const uint4*)(H2 + (size_t)c2 * F + off);
        uint4 r3 = *(const uint4*)(H2 + (size_t)c3 * F + off);
        const __half2* h0 = (const __half2*)&r0;
        const __half2* h1 = (const __half2*)&r1;
        const __half2* h2 = (const __half2*)&r2;
        const __half2* h3 = (const __half2*)&r3;
        #pragma unroll
        for (int j = 0; j < 4; j++) {
            __half2 hacc = __hmul2(w0, h0[j]);
            hacc = __hfma2(w1, h1[j], hacc);
            hacc = __hfma2(w2, h2[j], hacc);
            hacc = __hfma2(w3, h3[j], hacc);
            float2 f = __half22float2(hacc);
            acc[j*2]   += f.x;
            acc[j*2+1] += f.y;
        }
    }
    for (; e < e1; e++) {
        int c = g_pcol[e];
        float v = g_pval[e];
        uint4 rr = *(const uint4*)(H2 + (size_t)c * F + off);
        const __half2* hh = (const __half2*)&rr;
        #pragma unroll
        for (int j = 0; j < 4; j++) {
            float2 f = __half22float2(hh[j]);
            acc[j*2]   += v * f.x;
            acc[j*2+1] += v * f.y;
        }
    }

    #pragma unroll
    for (int j = 0; j < 8; j++)
        sin[sidx][hl * 8 + j] = acc[j] + b2[hl * 8 + j];
    #pragma unroll
    for (int j = 0; j < 4; j++)
        sin[sidx][F + hl * 4 + j] = s[(size_t)b * NSDIM + hl * 4 + j];
    __syncwarp();

    float z = bls[hl];
    #pragma unroll 4
    for (int k = 0; k < F + NSDIM; k++)
        z += sin[sidx][k] * Wls[k * NC + hl];

    float m = z;
    #pragma unroll
    for (int o = 8; o > 0; o >>= 1)
        m = fmaxf(m, __shfl_xor_sync(0xffffffffu, m, o, 16));
    float ex = expf(z - m);
    float sum = ex;
    #pragma unroll
    for (int o = 8; o > 0; o >>= 1)
        sum += __shfl_xor_sync(0xffffffffu, sum, o, 16);
    out[(size_t)b * NC + hl] = z - m - logf(sum);
}

// ---------------- launch ----------------
extern "C" void kernel_launch(void* const* d_in, const int* in_sizes, int n_in,
                              void* d_out, int out_size)
{
    const float* s    = (const float*)d_in[0];
    const float* x    = (const float*)d_in[1];
    const int*   row  = (const int*)  d_in[2];
    const int*   col  = (const int*)  d_in[3];
    const float* val  = (const float*)d_in[4];
    const int*   index= (const int*)  d_in[5];
    const float* W1   = (const float*)d_in[6];
    const float* b1   = (const float*)d_in[7];
    const float* W2   = (const float*)d_in[8];
    const float* b2   = (const float*)d_in[9];
    const float* Wl   = (const float*)d_in[10];
    const float* bl   = (const float*)d_in[11];
    float* out = (float*)d_out;

    __half *A, *B, *Wh;
    void *csp;
    cudaGetSymbolAddress((void**)&A, g_bufA);
    cudaGetSymbolAddress((void**)&B, g_bufB);
    cudaGetSymbolAddress((void**)&Wh, g_Wh);
    cudaGetSymbolAddress(&csp, g_cs);

    static cudaStream_t side = nullptr;
    static cudaEvent_t evFork = nullptr, evSide = nullptr;
    if (side == nullptr) {
        cudaStreamCreateWithFlags(&side, cudaStreamNonBlocking);
        cudaEventCreateWithFlags(&evFork, cudaEventDisableTiming);
        cudaEventCreateWithFlags(&evSide, cudaEventDisableTiming);
        cudaFuncSetAttribute((const void*)gemm128_fp16<false, false>, cudaFuncAttributeMaxDynamicSharedMemorySize, GEMM_SMEM);
        cudaFuncSetAttribute((const void*)gemm128_fp16<true, true>,   cudaFuncAttributeMaxDynamicSharedMemorySize, GEMM_SMEM);
    }

    const int gemm_grid  = (NN + 127) / 128;           // 782
    const int edge_grid  = (NEDGE + 255) / 256;        // 6250
    const int spmm_grid  = (NN + 15) / 16;             // 6250

    // fork: CSR + C* build on side stream
    cudaEventRecord(evFork, 0);
    cudaStreamWaitEvent(side, evFork, 0);
    cudaMemsetAsync(csp, 0, sizeof(CsrScratch), side);
    flagidx_kernel<<<(BQ + 255) / 256, 256, 0, side>>>(index);
    hist_kernel<<<edge_grid, 256, 0, side>>>(row, NEDGE);
    mark_kernel<<<edge_grid, 256, 0, side>>>(row, col, NEDGE);
    scan_fused<<<SCAN_NB, 256, 0, side>>>(NN, NEDGE);
    compact_kernel<<<SCAN_NB, 256, 0, side>>>(NN);
    scatter_kernel<<<edge_grid, 256, 0, side>>>(row, col, val, NEDGE);
    cudaEventRecord(evSide, side);

    // main stream: W transpose, then GEMM1 (concurrent with side build)
    wtrans_kernel<<<128, 256>>>(W1, W2);
    gemm128_fp16<false, false><<<gemm_grid, 256, GEMM_SMEM>>>(x, Wh, nullptr, A, NN);

    // join, then the dependent chain (restricted to C*)
    cudaStreamWaitEvent(0, evSide, 0);
    spmm_csr<<<spmm_grid, 256>>>(A, B);
    gemm128_fp16<true, true><<<gemm_grid, 256, GEMM_SMEM>>>(B, Wh + F * F, b1, A, NN);
    spmm2_final<<<(BQ + 15) / 16, 256>>>(A, b2, s, index, Wl, bl, out);
}

// round 13
// speedup vs baseline: 1.0160x; 1.0160x over previous
#include <cuda_runtime.h>
#include <cuda_fp16.h>
#include <cstdint>
#include <math.h>

#define NN      100000
#define NEDGE   1600000
#define F       128
#define BQ      8192
#define NSDIM   64
#define NC      16
#define SCAN_NB ((NN + 1023) / 1024)   // 98

// ---------------- scratch (__device__ globals, allocation-free) ----------------
__device__ __half g_bufA[(size_t)NN * F];
__device__ __half g_bufB[(size_t)NN * F];
__device__ __half g_Wh[2][F * F];      // W1,W2 transposed [n][k], fp16

struct CsrScratch {              // zeroed with ONE memset per launch
    int cnt[NN];                 // edge histogram
    int iflag[NN];               // node is in index set
    int flag[NN];                // node is in C* (needed by final)
    int bsum[128];               // csr scan block sums
    int lsum[128];               // list scan block sums
    unsigned int ctr;            // csr scan barrier
    unsigned int lctr;           // list scan barrier
    unsigned int pad[2];
};
__device__ CsrScratch g_cs;
__device__ int   g_ptr[NN + 1];
__device__ int   g_woff[NN];
__device__ int   g_pcol[NEDGE];
__device__ float g_pval[NEDGE];
__device__ int   g_list[NN];     // compacted C* rows
__device__ int   g_nlist;        // |C*|

// fp16 GEMM smem: As2 [128 m][68] half2-as-u32, Ws2 [128 n][68] half2-as-u32
#define S2 68
#define GEMM_SMEM (2 * 128 * S2 * 4)   // 69632 B -> 2 blocks/SM

// ---------------- W transpose+convert: W[k][n] fp32 -> g_Wh[w][n][k] fp16 ----------------
__global__ void wtrans_kernel(const float* __restrict__ W1, const float* __restrict__ W2)
{
    int idx = blockIdx.x * blockDim.x + threadIdx.x;   // 32768 total
    int w   = idx >> 14;
    int rem = idx & 16383;
    int k   = rem >> 7;
    int n   = rem & 127;
    const float* Wsrc = (w == 0) ? W1 : W2;
    g_Wh[w][n * F + k] = __float2half_rn(Wsrc[k * F + n]);
}

// ---------------- fp16 tensor-core GEMM: C[M,128](fp16) = transform(X) @ W ----------------
// FUSE=false: X fp32.  FUSE=true: X fp16, relu(x + bias).
// LIST=true: rows indirected through g_list[0..g_nlist).
template <bool FUSE, bool LIST>
__global__ void gemm128_fp16(const void* __restrict__ Xv, const __half* __restrict__ Wh,
                             const float* __restrict__ bias, __half* __restrict__ C, int M)
{
    extern __shared__ unsigned int smu[];
    unsigned int* As2 = smu;             // [128][S2]  rows m, half2 along k
    unsigned int* Ws2 = smu + 128 * S2;  // [128][S2]  rows n, half2 along k

    const int tid  = threadIdx.x;          // 256 threads, 8 warps
    const int wid  = tid >> 5;
    const int lane = tid & 31;
    const int gid  = lane >> 2;            // 0..7
    const int tig  = lane & 3;             // 0..3
    const int wm   = wid & 3;              // 4 warps over M (32 rows each)
    const int wn   = wid >> 2;             // 2 warps over N (64 cols each)
    const int m0   = blockIdx.x * 128;

    const int nl = LIST ? g_nlist : M;
    if (LIST && m0 >= nl) return;

    // W fp16 [n][k] -> Ws2: 2048 uint4 / 256 thr = 8 vec iters
    #pragma unroll
    for (int i = 0; i < 8; i++) {
        int idx = i * 256 + tid;
        int n = idx >> 4;
        int j = idx & 15;
        uint4 u = ((const uint4*)Wh)[idx];
        *(uint4*)(Ws2 + n * S2 + j * 4) = u;
    }

    // X tile -> As2[m][k/2] half2
    if (FUSE) {
        const __half* Xh = (const __half*)Xv;
        #pragma unroll
        for (int i = 0; i < 8; i++) {
            int idx = i * 256 + tid;        // 2048 chunks of 8 halves
            int m  = idx >> 4;
            int k8 = (idx & 15) << 3;
            int gm = m0 + m;
            bool valid = gm < nl;
            int src = (LIST && valid) ? g_list[gm] : gm;
            uint4 raw = make_uint4(0u, 0u, 0u, 0u);
            if (valid) raw = *(const uint4*)(Xh + (size_t)src * F + k8);
            const __half2* hp = (const __half2*)&raw;
            unsigned int o[4];
            #pragma unroll
            for (int j = 0; j < 4; j++) {
                float2 f = __half22float2(hp[j]);
                float2 bb = *(const float2*)(bias + k8 + j * 2);
                f.x = fmaxf(f.x + bb.x, 0.f);
                f.y = fmaxf(f.y + bb.y, 0.f);
                __half2 h = __floats2half2_rn(f.x, f.y);
                o[j] = *(unsigned int*)&h;
            }
            int base = m * S2 + (k8 >> 1);
            *(uint2*)(As2 + base)     = make_uint2(o[0], o[1]);
            *(uint2*)(As2 + base + 2) = make_uint2(o[2], o[3]);
        }
    } else {
        const float* Xf = (const float*)Xv;
        #pragma unroll
        for (int i = 0; i < 16; i++) {
            int idx = i * 256 + tid;        // 4096 float4
            int m  = idx >> 5;
            int k4 = (idx & 31) << 2;
            int gm = m0 + m;
            float4 v = make_float4(0.f, 0.f, 0.f, 0.f);
            if (gm < nl) v = *(const float4*)(Xf + (size_t)gm * F + k4);
            __half2 h0 = __floats2half2_rn(v.x, v.y);
            __half2 h1 = __floats2half2_rn(v.z, v.w);
            int base = m * S2 + (k4 >> 1);
            *(uint2*)(As2 + base) = make_uint2(*(unsigned int*)&h0, *(unsigned int*)&h1);
        }
    }
    __syncthreads();

    float acc[2][8][4];
    #pragma unroll
    for (int a = 0; a < 2; a++)
        #pragma unroll
        for (int b = 0; b < 8; b++)
            #pragma unroll
            for (int c = 0; c < 4; c++) acc[a][b][c] = 0.f;

    // 8 k-steps of 16
    #pragma unroll
    for (int ks = 0; ks < 8; ks++) {
        const int k0h = ks * 8;
        unsigned int afr[2][4];
        #pragma unroll
        for (int mf = 0; mf < 2; mf++) {
            int rb = wm * 32 + mf * 16 + gid;
            afr[mf][0] = As2[rb * S2 + k0h + tig];
            afr[mf][1] = As2[(rb + 8) * S2 + k0h + tig];
            afr[mf][2] = As2[rb * S2 + k0h + 4 + tig];
            afr[mf][3] = As2[(rb + 8) * S2 + k0h + 4 + tig];
        }
        unsigned int bfr[8][2];
        #pragma unroll
        for (int nf = 0; nf < 8; nf++) {
            int nb = wn * 64 + nf * 8 + gid;
            bfr[nf][0] = Ws2[nb * S2 + k0h + tig];
            bfr[nf][1] = Ws2[nb * S2 + k0h + 4 + tig];
        }
        #pragma unroll
        for (int mf = 0; mf < 2; mf++)
            #pragma unroll
            for (int nf = 0; nf < 8; nf++) {
                asm volatile(
                    "mma.sync.aligned.m16n8k16.row.col.f32.f16.f16.f32 "
                    "{%0,%1,%2,%3}, {%4,%5,%6,%7}, {%8,%9}, {%0,%1,%2,%3};"
                    : "+f"(acc[mf][nf][0]), "+f"(acc[mf][nf][1]),
                      "+f"(acc[mf][nf][2]), "+f"(acc[mf][nf][3])
                    : "r"(afr[mf][0]), "r"(afr[mf][1]), "r"(afr[mf][2]), "r"(afr[mf][3]),
                      "r"(bfr[nf][0]), "r"(bfr[nf][1]));
            }
    }

    #pragma unroll
    for (int mf = 0; mf < 2; mf++) {
        int r0 = m0 + wm * 32 + mf * 16 + gid;
        bool v0 = r0 < nl;
        bool v1 = r0 + 8 < nl;
        int d0 = (LIST && v0) ? g_list[r0] : r0;
        int d1 = (LIST && v1) ? g_list[r0 + 8] : r0 + 8;
        #pragma unroll
        for (int nf = 0; nf < 8; nf++) {
            int ccol = wn * 64 + nf * 8 + tig * 2;
            if (v0)
                *(__half2*)(C + (size_t)d0 * F + ccol) =
                    __floats2half2_rn(acc[mf][nf][0], acc[mf][nf][1]);
            if (v1)
                *(__half2*)(C + (size_t)d1 * F + ccol) =
                    __floats2half2_rn(acc[mf][nf][2], acc[mf][nf][3]);
        }
    }
}

// ---------------- CSR + C* build kernels ----------------
__global__ void flagidx_kernel(const int* __restrict__ index)
{
    int b = blockIdx.x * blockDim.x + threadIdx.x;
    if (b < BQ) g_cs.iflag[index[b]] = 1;
}

// fused: histogram + C* mark in one edge pass
__global__ void histmark_kernel(const int* __restrict__ row, const int* __restrict__ col, int ne)
{
    int e = blockIdx.x * blockDim.x + threadIdx.x;
    if (e < ne) {
        int r = row[e];
        atomicAdd(&g_cs.cnt[r], 1);
        if (g_cs.iflag[r]) g_cs.flag[col[e]] = 1;
    }
}

// fused: CSR exclusive scan (phase 1) + C* compaction (phase 2), one launch
__global__ void scan_compact(int n, int ne)
{
    __shared__ int sm[256];
    __shared__ int wsum[8];
    __shared__ int s_prefix;
    const int tid = threadIdx.x;
    const int bid = blockIdx.x;
    const int nb  = gridDim.x;
    const int base = bid * 1024 + tid * 4;

    // ---- phase 1: cnt -> g_ptr / g_woff ----
    {
        int v[4];
        #pragma unroll
        for (int i = 0; i < 4; i++)
            v[i] = (base + i < n) ? g_cs.cnt[base + i] : 0;
        int tsum = v[0] + v[1] + v[2] + v[3];
        sm[tid] = tsum;
        __syncthreads();
        #pragma unroll
        for (int o = 1; o < 256; o <<= 1) {
            int t = (tid >= o) ? sm[tid - o] : 0;
            __syncthreads();
            sm[tid] += t;
            __syncthreads();
        }
        if (tid == 0) {
            ((volatile int*)g_cs.bsum)[bid] = sm[255];
            __threadfence();
            atomicAdd(&g_cs.ctr, 1u);
            while (((volatile unsigned int*)&g_cs.ctr)[0] < (unsigned)nb) {}
            __threadfence();
        }
        __syncthreads();
        int p = (tid < bid) ? ((volatile int*)g_cs.bsum)[tid] : 0;
        #pragma unroll
        for (int o = 16; o; o >>= 1) p += __shfl_xor_sync(0xffffffffu, p, o);
        if ((tid & 31) == 0) wsum[tid >> 5] = p;
        __syncthreads();
        if (tid < 8) {
            int q = wsum[tid];
            #pragma unroll
            for (int o = 4; o; o >>= 1) q += __shfl_xor_sync(0xffu, q, o);
            if (tid == 0) s_prefix = q;
        }
        __syncthreads();
        int run = s_prefix + sm[tid] - tsum;
        #pragma unroll
        for (int i = 0; i < 4; i++) {
            if (base + i < n) { g_ptr[base + i] = run; g_woff[base + i] = run; }
            run += v[i];
        }
        if (bid == nb - 1 && tid == 0) g_ptr[n] = ne;
    }
    __syncthreads();

    // ---- phase 2: flag -> g_list / g_nlist ----
    {
        int v[4];
        #pragma unroll
        for (int i = 0; i < 4; i++)
            v[i] = (base + i < n) ? g_cs.flag[base + i] : 0;
        int tsum = v[0] + v[1] + v[2] + v[3];
        sm[tid] = tsum;
        __syncthreads();
        #pragma unroll
        for (int o = 1; o < 256; o <<= 1) {
            int t = (tid >= o) ? sm[tid - o] : 0;
            __syncthreads();
            sm[tid] += t;
            __syncthreads();
        }
        if (tid == 0) {
            ((volatile int*)g_cs.lsum)[bid] = sm[255];
            __threadfence();
            atomicAdd(&g_cs.lctr, 1u);
            while (((volatile unsigned int*)&g_cs.lctr)[0] < (unsigned)nb) {}
            __threadfence();
        }
        __syncthreads();
        int p = (tid < bid) ? ((volatile int*)g_cs.lsum)[tid] : 0;
        #pragma unroll
        for (int o = 16; o; o >>= 1) p += __shfl_xor_sync(0xffffffffu, p, o);
        if ((tid & 31) == 0) wsum[tid >> 5] = p;
        __syncthreads();
        if (tid < 8) {
            int q = wsum[tid];
            #pragma unroll
            for (int o = 4; o; o >>= 1) q += __shfl_xor_sync(0xffu, q, o);
            if (tid == 0) s_prefix = q;
        }
        __syncthreads();
        int run = s_prefix + sm[tid] - tsum;
        #pragma unroll
        for (int i = 0; i < 4; i++) {
            if (base + i < n && v[i]) g_list[run] = base + i;
            run += v[i];
        }
        if (bid == nb - 1 && tid == 255) g_nlist = run;
    }
}

__global__ void scatter_kernel(const int* __restrict__ row, const int* __restrict__ col,
                               const float* __restrict__ val, int ne)
{
    int e = blockIdx.x * blockDim.x + threadIdx.x;
    if (e < ne) {
        int r = row[e];
        int p = atomicAdd(&g_woff[r], 1);
        g_pcol[p] = col[e];
        g_pval[p] = val[e];
    }
}

// ---------------- SPMM1 over compacted C* rows ----------------
__global__ void __launch_bounds__(256, 6)
spmm_csr(const __half* __restrict__ H, __half* __restrict__ out)
{
    const int tid  = threadIdx.x;     // 256 thr = 16 list entries/block
    const int warp = tid >> 5;
    const int lane = tid & 31;
    const int half = lane >> 4;
    const int hl   = lane & 15;
    int li = blockIdx.x * 16 + warp * 2 + half;
    if (li >= g_nlist) return;
    int r = g_list[li];

    int e0 = g_ptr[r];
    int e1 = g_ptr[r + 1];

    float acc[8] = {0.f, 0.f, 0.f, 0.f, 0.f, 0.f, 0.f, 0.f};
    const size_t off = (size_t)hl * 8;

    int e = e0;
    for (; e + 4 <= e1; e += 4) {
        int   c0 = g_pcol[e],     c1 = g_pcol[e + 1], c2 = g_pcol[e + 2], c3 = g_pcol[e + 3];
        float v0 = g_pval[e],     v1 = g_pval[e + 1], v2 = g_pval[e + 2], v3 = g_pval[e + 3];
        __half2 w0 = __float2half2_rn(v0);
        __half2 w1 = __float2half2_rn(v1);
        __half2 w2 = __float2half2_rn(v2);
        __half2 w3 = __float2half2_rn(v3);
        uint4 r0 = *(const uint4*)(H + (size_t)c0 * F + off);
        uint4 r1 = *(const uint4*)(H + (size_t)c1 * F + off);
        uint4 r2 = *(const uint4*)(H + (size_t)c2 * F + off);
        uint4 r3 = *(const uint4*)(H + (size_t)c3 * F + off);
        const __half2* h0 = (const __half2*)&r0;
        const __half2* h1 = (const __half2*)&r1;
        const __half2* h2 = (const __half2*)&r2;
        const __half2* h3 = (const __half2*)&r3;
        #pragma unroll
        for (int j = 0; j < 4; j++) {
            __half2 hacc = __hmul2(w0, h0[j]);
            hacc = __hfma2(w1, h1[j], hacc);
            hacc = __hfma2(w2, h2[j], hacc);
            hacc = __hfma2(w3, h3[j], hacc);
            float2 f = __half22float2(hacc);
            acc[j*2]   += f.x;
            acc[j*2+1] += f.y;
        }
    }
    for (; e < e1; e++) {
        int c = g_pcol[e];
        float v = g_pval[e];
        uint4 rr = *(const uint4*)(H + (size_t)c * F + off);
        const __half2* hh = (const __half2*)&rr;
        #pragma unroll
        for (int j = 0; j < 4; j++) {
            float2 f = __half22float2(hh[j]);
            acc[j*2]   += v * f.x;
            acc[j*2+1] += v * f.y;
        }
    }
    uint4 o;
    __half2* op = (__half2*)&o;
    #pragma unroll
    for (int j = 0; j < 4; j++)
        op[j] = __floats2half2_rn(acc[j*2], acc[j*2+1]);
    *(uint4*)(out + (size_t)r * F + off) = o;
}

// ---------------- fused: row-restricted SPMM2 + linear + log_softmax ----------------
__global__ void __launch_bounds__(256, 6)
spmm2_final(const __half* __restrict__ H2, const float* __restrict__ b2,
            const float* __restrict__ s, const int* __restrict__ index,
            const float* __restrict__ Wl, const float* __restrict__ bl,
            float* __restrict__ out)
{
    __shared__ float Wls[(F + NSDIM) * NC];
    __shared__ float bls[NC];
    __shared__ float sin[16][F + NSDIM];

    for (int i = threadIdx.x; i < (F + NSDIM) * NC; i += blockDim.x) Wls[i] = Wl[i];
    if (threadIdx.x < NC) bls[threadIdx.x] = bl[threadIdx.x];
    __syncthreads();

    const int tid  = threadIdx.x;
    const int warp = tid >> 5;
    const int lane = tid & 31;
    const int half = lane >> 4;
    const int hl   = lane & 15;
    const int sidx = warp * 2 + half;
    int b = blockIdx.x * 16 + sidx;
    if (b >= BQ) return;

    int r = __ldg(index + b);
    int e0 = g_ptr[r];
    int e1 = g_ptr[r + 1];

    float acc[8] = {0.f, 0.f, 0.f, 0.f, 0.f, 0.f, 0.f, 0.f};
    const size_t off = (size_t)hl * 8;

    int e = e0;
    for (; e + 4 <= e1; e += 4) {
        int   c0 = g_pcol[e],     c1 = g_pcol[e + 1], c2 = g_pcol[e + 2], c3 = g_pcol[e + 3];
        float v0 = g_pval[e],     v1 = g_pval[e + 1], v2 = g_pval[e + 2], v3 = g_pval[e + 3];
        __half2 w0 = __float2half2_rn(v0);
        __half2 w1 = __float2half2_rn(v1);
        __half2 w2 = __float2half2_rn(v2);
        __half2 w3 = __float2half2_rn(v3);
        uint4 r0 = *(const uint4*)(H2 + (size_t)c0 * F + off);
        uint4 r1 = *(const uint4*)(H2 + (size_t)c1 * F + off);
        uint4 r2 = *(const uint4*)(H2 + (size_t)c2 * F + off);
        uint4 r3 = *(const uint4*)(H2 + (size_t)c3 * F + off);
        const __half2* h0 = (const __half2*)&r0;
        const __half2* h1 = (const __half2*)&r1;
        const __half2* h2 = (const __half2*)&r2;
        const __half2* h3 = (const __half2*)&r3;
        #pragma unroll
        for (int j = 0; j < 4; j++) {
            __half2 hacc = __hmul2(w0, h0[j]);
            hacc = __hfma2(w1, h1[j], hacc);
            hacc = __hfma2(w2, h2[j], hacc);
            hacc = __hfma2(w3, h3[j], hacc);
            float2 f = __half22float2(hacc);
            acc[j*2]   += f.x;
            acc[j*2+1] += f.y;
        }
    }
    for (; e < e1; e++) {
        int c = g_pcol[e];
        float v = g_pval[e];
        uint4 rr = *(const uint4*)(H2 + (size_t)c * F + off);
        const __half2* hh = (const __half2*)&rr;
        #pragma unroll
        for (int j = 0; j < 4; j++) {
            float2 f = __half22float2(hh[j]);
            acc[j*2]   += v * f.x;
            acc[j*2+1] += v * f.y;
        }
    }

    #pragma unroll
    for (int j = 0; j < 8; j++)
        sin[sidx][hl * 8 + j] = acc[j] + b2[hl * 8 + j];
    #pragma unroll
    for (int j = 0; j < 4; j++)
        sin[sidx][F + hl * 4 + j] = s[(size_t)b * NSDIM + hl * 4 + j];
    __syncwarp();

    float z = bls[hl];
    #pragma unroll 4
    for (int k = 0; k < F + NSDIM; k++)
        z += sin[sidx][k] * Wls[k * NC + hl];

    float m = z;
    #pragma unroll
    for (int o = 8; o > 0; o >>= 1)
        m = fmaxf(m, __shfl_xor_sync(0xffffffffu, m, o, 16));
    float ex = expf(z - m);
    float sum = ex;
    #pragma unroll
    for (int o = 8; o > 0; o >>= 1)
        sum += __shfl_xor_sync(0xffffffffu, sum, o, 16);
    out[(size_t)b * NC + hl] = z - m - logf(sum);
}

// ---------------- launch ----------------
extern "C" void kernel_launch(void* const* d_in, const int* in_sizes, int n_in,
                              void* d_out, int out_size)
{
    const float* s    = (const float*)d_in[0];
    const float* x    = (const float*)d_in[1];
    const int*   row  = (const int*)  d_in[2];
    const int*   col  = (const int*)  d_in[3];
    const float* val  = (const float*)d_in[4];
    const int*   index= (const int*)  d_in[5];
    const float* W1   = (const float*)d_in[6];
    const float* b1   = (const float*)d_in[7];
    const float* W2   = (const float*)d_in[8];
    const float* b2   = (const float*)d_in[9];
    const float* Wl   = (const float*)d_in[10];
    const float* bl   = (const float*)d_in[11];
    float* out = (float*)d_out;

    __half *A, *B, *Wh;
    void *csp;
    cudaGetSymbolAddress((void**)&A, g_bufA);
    cudaGetSymbolAddress((void**)&B, g_bufB);
    cudaGetSymbolAddress((void**)&Wh, g_Wh);
    cudaGetSymbolAddress(&csp, g_cs);

    static cudaStream_t side = nullptr;
    static cudaEvent_t evFork = nullptr, evSide = nullptr;
    if (side == nullptr) {
        cudaStreamCreateWithFlags(&side, cudaStreamNonBlocking);
        cudaEventCreateWithFlags(&evFork, cudaEventDisableTiming);
        cudaEventCreateWithFlags(&evSide, cudaEventDisableTiming);
        cudaFuncSetAttribute((const void*)gemm128_fp16<false, false>, cudaFuncAttributeMaxDynamicSharedMemorySize, GEMM_SMEM);
        cudaFuncSetAttribute((const void*)gemm128_fp16<true, true>,   cudaFuncAttributeMaxDynamicSharedMemorySize, GEMM_SMEM);
    }

    const int gemm_grid  = (NN + 127) / 128;           // 782
    const int edge_grid  = (NEDGE + 255) / 256;        // 6250
    const int spmm_grid  = (NN + 15) / 16;             // 6250

    // fork: CSR + C* build on side stream (5 nodes)
    cudaEventRecord(evFork, 0);
    cudaStreamWaitEvent(side, evFork, 0);
    cudaMemsetAsync(csp, 0, sizeof(CsrScratch), side);
    flagidx_kernel<<<(BQ + 255) / 256, 256, 0, side>>>(index);
    histmark_kernel<<<edge_grid, 256, 0, side>>>(row, col, NEDGE);
    scan_compact<<<SCAN_NB, 256, 0, side>>>(NN, NEDGE);
    scatter_kernel<<<edge_grid, 256, 0, side>>>(row, col, val, NEDGE);
    cudaEventRecord(evSide, side);

    // main stream: W transpose, then GEMM1 (concurrent with side build)
    wtrans_kernel<<<128, 256>>>(W1, W2);
    gemm128_fp16<false, false><<<gemm_grid, 256, GEMM_SMEM>>>(x, Wh, nullptr, A, NN);

    // join, then the dependent chain (restricted to C*)
    cudaStreamWaitEvent(0, evSide, 0);
    spmm_csr<<<spmm_grid, 256>>>(A, B);
    gemm128_fp16<true, true><<<gemm_grid, 256, GEMM_SMEM>>>(B, Wh + F * F, b1, A, NN);
    spmm2_final<<<(BQ + 15) / 16, 256>>>(A, b2, s, index, Wl, bl, out);
}

// round 14
// speedup vs baseline: 1.0746x; 1.0577x over previous
#include <cuda_runtime.h>
#include <cuda_fp16.h>
#include <cstdint>
#include <math.h>

#define NN      100000
#define NEDGE   1600000
#define F       128
#define BQ      8192
#define NSDIM   64
#define NC      16
#define SCAN_NB ((NN + 1023) / 1024)   // 98

// ---------------- scratch (__device__ globals, allocation-free) ----------------
__device__ __half g_bufA[(size_t)NN * F];
__device__ __half g_bufB[(size_t)NN * F];
__device__ __half g_Wh[2][F * F];      // W1,W2 transposed [n][k], fp16

struct CsrScratch {              // zeroed with ONE memset per launch
    int cnt[NN];                 // edge histogram
    int iflag[NN];               // node is in index set
    int flag[NN];                // node is in C* (needed by final)
    int bsum[128];               // csr scan block sums
    int lsum[128];               // list scan block sums
    unsigned int ctr;            // csr scan barrier
    unsigned int lctr;           // list scan barrier
    unsigned int pad[2];
};
__device__ CsrScratch g_cs;
__device__ int   g_ptr[NN + 1];
__device__ int   g_woff[NN];
__device__ int2  g_edge[NEDGE];  // packed (col, val-bits)
__device__ int   g_list[NN];     // compacted C* rows
__device__ int   g_nlist;        // |C*|

// fp16 GEMM smem: As2 [128 m][68] half2-as-u32, Ws2 [128 n][68] half2-as-u32
#define S2 68
#define GEMM_SMEM (2 * 128 * S2 * 4)   // 69632 B -> 2 blocks/SM

// ---------------- W transpose+convert: W[k][n] fp32 -> g_Wh[w][n][k] fp16 ----------------
__global__ void wtrans_kernel(const float* __restrict__ W1, const float* __restrict__ W2)
{
    int idx = blockIdx.x * blockDim.x + threadIdx.x;   // 32768 total
    int w   = idx >> 14;
    int rem = idx & 16383;
    int k   = rem >> 7;
    int n   = rem & 127;
    const float* Wsrc = (w == 0) ? W1 : W2;
    g_Wh[w][n * F + k] = __float2half_rn(Wsrc[k * F + n]);
}

// ---------------- fp16 tensor-core GEMM ----------------
template <bool FUSE, bool LIST>
__global__ void gemm128_fp16(const void* __restrict__ Xv, const __half* __restrict__ Wh,
                             const float* __restrict__ bias, __half* __restrict__ C, int M)
{
    extern __shared__ unsigned int smu[];
    unsigned int* As2 = smu;             // [128][S2]
    unsigned int* Ws2 = smu + 128 * S2;  // [128][S2]

    const int tid  = threadIdx.x;
    const int wid  = tid >> 5;
    const int lane = tid & 31;
    const int gid  = lane >> 2;
    const int tig  = lane & 3;
    const int wm   = wid & 3;
    const int wn   = wid >> 2;
    const int m0   = blockIdx.x * 128;

    const int nl = LIST ? g_nlist : M;
    if (LIST && m0 >= nl) return;

    #pragma unroll
    for (int i = 0; i < 8; i++) {
        int idx = i * 256 + tid;
        int n = idx >> 4;
        int j = idx & 15;
        uint4 u = ((const uint4*)Wh)[idx];
        *(uint4*)(Ws2 + n * S2 + j * 4) = u;
    }

    if (FUSE) {
        const __half* Xh = (const __half*)Xv;
        #pragma unroll
        for (int i = 0; i < 8; i++) {
            int idx = i * 256 + tid;
            int m  = idx >> 4;
            int k8 = (idx & 15) << 3;
            int gm = m0 + m;
            bool valid = gm < nl;
            int src = (LIST && valid) ? g_list[gm] : gm;
            uint4 raw = make_uint4(0u, 0u, 0u, 0u);
            if (valid) raw = *(const uint4*)(Xh + (size_t)src * F + k8);
            const __half2* hp = (const __half2*)&raw;
            unsigned int o[4];
            #pragma unroll
            for (int j = 0; j < 4; j++) {
                float2 f = __half22float2(hp[j]);
                float2 bb = *(const float2*)(bias + k8 + j * 2);
                f.x = fmaxf(f.x + bb.x, 0.f);
                f.y = fmaxf(f.y + bb.y, 0.f);
                __half2 h = __floats2half2_rn(f.x, f.y);
                o[j] = *(unsigned int*)&h;
            }
            int base = m * S2 + (k8 >> 1);
            *(uint2*)(As2 + base)     = make_uint2(o[0], o[1]);
            *(uint2*)(As2 + base + 2) = make_uint2(o[2], o[3]);
        }
    } else {
        const float* Xf = (const float*)Xv;
        #pragma unroll
        for (int i = 0; i < 16; i++) {
            int idx = i * 256 + tid;
            int m  = idx >> 5;
            int k4 = (idx & 31) << 2;
            int gm = m0 + m;
            float4 v = make_float4(0.f, 0.f, 0.f, 0.f);
            if (gm < nl) v = *(const float4*)(Xf + (size_t)gm * F + k4);
            __half2 h0 = __floats2half2_rn(v.x, v.y);
            __half2 h1 = __floats2half2_rn(v.z, v.w);
            int base = m * S2 + (k4 >> 1);
            *(uint2*)(As2 + base) = make_uint2(*(unsigned int*)&h0, *(unsigned int*)&h1);
        }
    }
    __syncthreads();

    float acc[2][8][4];
    #pragma unroll
    for (int a = 0; a < 2; a++)
        #pragma unroll
        for (int b = 0; b < 8; b++)
            #pragma unroll
            for (int c = 0; c < 4; c++) acc[a][b][c] = 0.f;

    #pragma unroll
    for (int ks = 0; ks < 8; ks++) {
        const int k0h = ks * 8;
        unsigned int afr[2][4];
        #pragma unroll
        for (int mf = 0; mf < 2; mf++) {
            int rb = wm * 32 + mf * 16 + gid;
            afr[mf][0] = As2[rb * S2 + k0h + tig];
            afr[mf][1] = As2[(rb + 8) * S2 + k0h + tig];
            afr[mf][2] = As2[rb * S2 + k0h + 4 + tig];
            afr[mf][3] = As2[(rb + 8) * S2 + k0h + 4 + tig];
        }
        unsigned int bfr[8][2];
        #pragma unroll
        for (int nf = 0; nf < 8; nf++) {
            int nb = wn * 64 + nf * 8 + gid;
            bfr[nf][0] = Ws2[nb * S2 + k0h + tig];
            bfr[nf][1] = Ws2[nb * S2 + k0h + 4 + tig];
        }
        #pragma unroll
        for (int mf = 0; mf < 2; mf++)
            #pragma unroll
            for (int nf = 0; nf < 8; nf++) {
                asm volatile(
                    "mma.sync.aligned.m16n8k16.row.col.f32.f16.f16.f32 "
                    "{%0,%1,%2,%3}, {%4,%5,%6,%7}, {%8,%9}, {%0,%1,%2,%3};"
                    : "+f"(acc[mf][nf][0]), "+f"(acc[mf][nf][1]),
                      "+f"(acc[mf][nf][2]), "+f"(acc[mf][nf][3])
                    : "r"(afr[mf][0]), "r"(afr[mf][1]), "r"(afr[mf][2]), "r"(afr[mf][3]),
                      "r"(bfr[nf][0]), "r"(bfr[nf][1]));
            }
    }

    #pragma unroll
    for (int mf = 0; mf < 2; mf++) {
        int r0 = m0 + wm * 32 + mf * 16 + gid;
        bool v0 = r0 < nl;
        bool v1 = r0 + 8 < nl;
        int d0 = (LIST && v0) ? g_list[r0] : r0;
        int d1 = (LIST && v1) ? g_list[r0 + 8] : r0 + 8;
        #pragma unroll
        for (int nf = 0; nf < 8; nf++) {
            int ccol = wn * 64 + nf * 8 + tig * 2;
            if (v0)
                *(__half2*)(C + (size_t)d0 * F + ccol) =
                    __floats2half2_rn(acc[mf][nf][0], acc[mf][nf][1]);
            if (v1)
                *(__half2*)(C + (size_t)d1 * F + ccol) =
                    __floats2half2_rn(acc[mf][nf][2], acc[mf][nf][3]);
        }
    }
}

// ---------------- CSR + C* build kernels ----------------
__global__ void flagidx_kernel(const int* __restrict__ index)
{
    int b = blockIdx.x * blockDim.x + threadIdx.x;
    if (b < BQ) g_cs.iflag[index[b]] = 1;
}

// fused: histogram + C* mark in one edge pass
__global__ void histmark_kernel(const int* __restrict__ row, const int* __restrict__ col, int ne)
{
    int e = blockIdx.x * blockDim.x + threadIdx.x;
    if (e < ne) {
        int r = row[e];
        atomicAdd(&g_cs.cnt[r], 1);
        if (g_cs.iflag[r]) g_cs.flag[col[e]] = 1;
    }
}

// fused: CSR exclusive scan (phase 1) + C* compaction (phase 2)
__global__ void scan_compact(int n, int ne)
{
    __shared__ int sm[256];
    __shared__ int wsum[8];
    __shared__ int s_prefix;
    const int tid = threadIdx.x;
    const int bid = blockIdx.x;
    const int nb  = gridDim.x;
    const int base = bid * 1024 + tid * 4;

    // ---- phase 1: cnt -> g_ptr / g_woff ----
    {
        int v[4];
        #pragma unroll
        for (int i = 0; i < 4; i++)
            v[i] = (base + i < n) ? g_cs.cnt[base + i] : 0;
        int tsum = v[0] + v[1] + v[2] + v[3];
        sm[tid] = tsum;
        __syncthreads();
        #pragma unroll
        for (int o = 1; o < 256; o <<= 1) {
            int t = (tid >= o) ? sm[tid - o] : 0;
            __syncthreads();
            sm[tid] += t;
            __syncthreads();
        }
        if (tid == 0) {
            ((volatile int*)g_cs.bsum)[bid] = sm[255];
            __threadfence();
            atomicAdd(&g_cs.ctr, 1u);
            while (((volatile unsigned int*)&g_cs.ctr)[0] < (unsigned)nb) {}
            __threadfence();
        }
        __syncthreads();
        int p = (tid < bid) ? ((volatile int*)g_cs.bsum)[tid] : 0;
        #pragma unroll
        for (int o = 16; o; o >>= 1) p += __shfl_xor_sync(0xffffffffu, p, o);
        if ((tid & 31) == 0) wsum[tid >> 5] = p;
        __syncthreads();
        if (tid < 8) {
            int q = wsum[tid];
            #pragma unroll
            for (int o = 4; o; o >>= 1) q += __shfl_xor_sync(0xffu, q, o);
            if (tid == 0) s_prefix = q;
        }
        __syncthreads();
        int run = s_prefix + sm[tid] - tsum;
        #pragma unroll
        for (int i = 0; i < 4; i++) {
            if (base + i < n) { g_ptr[base + i] = run; g_woff[base + i] = run; }
            run += v[i];
        }
        if (bid == nb - 1 && tid == 0) g_ptr[n] = ne;
    }
    __syncthreads();

    // ---- phase 2: flag -> g_list / g_nlist ----
    {
        int v[4];
        #pragma unroll
        for (int i = 0; i < 4; i++)
            v[i] = (base + i < n) ? g_cs.flag[base + i] : 0;
        int tsum = v[0] + v[1] + v[2] + v[3];
        sm[tid] = tsum;
        __syncthreads();
        #pragma unroll
        for (int o = 1; o < 256; o <<= 1) {
            int t = (tid >= o) ? sm[tid - o] : 0;
            __syncthreads();
            sm[tid] += t;
            __syncthreads();
        }
        if (tid == 0) {
            ((volatile int*)g_cs.lsum)[bid] = sm[255];
            __threadfence();
            atomicAdd(&g_cs.lctr, 1u);
            while (((volatile unsigned int*)&g_cs.lctr)[0] < (unsigned)nb) {}
            __threadfence();
        }
        __syncthreads();
        int p = (tid < bid) ? ((volatile int*)g_cs.lsum)[tid] : 0;
        #pragma unroll
        for (int o = 16; o; o >>= 1) p += __shfl_xor_sync(0xffffffffu, p, o);
        if ((tid & 31) == 0) wsum[tid >> 5] = p;
        __syncthreads();
        if (tid < 8) {
            int q = wsum[tid];
            #pragma unroll
            for (int o = 4; o; o >>= 1) q += __shfl_xor_sync(0xffu, q, o);
            if (tid == 0) s_prefix = q;
        }
        __syncthreads();
        int run = s_prefix + sm[tid] - tsum;
        #pragma unroll
        for (int i = 0; i < 4; i++) {
            if (base + i < n && v[i]) g_list[run] = base + i;
            run += v[i];
        }
        if (bid == nb - 1 && tid == 255) g_nlist = run;
    }
}

// scatter only edges whose row is ever read (C* or index), packed int2 store
__global__ void scatter_kernel(const int* __restrict__ row, const int* __restrict__ col,
                               const float* __restrict__ val, int ne)
{
    int e = blockIdx.x * blockDim.x + threadIdx.x;
    if (e < ne) {
        int r = row[e];
        if (g_cs.flag[r] | g_cs.iflag[r]) {
            int p = atomicAdd(&g_woff[r], 1);
            g_edge[p] = make_int2(col[e], __float_as_int(val[e]));
        }
    }
}

// ---------------- SPMM1 over compacted C* rows (int2 edges) ----------------
__global__ void __launch_bounds__(256, 6)
spmm_csr(const __half* __restrict__ H, __half* __restrict__ out)
{
    const int tid  = threadIdx.x;
    const int warp = tid >> 5;
    const int lane = tid & 31;
    const int half = lane >> 4;
    const int hl   = lane & 15;
    int li = blockIdx.x * 16 + warp * 2 + half;
    if (li >= g_nlist) return;
    int r = g_list[li];

    int e0 = g_ptr[r];
    int e1 = g_ptr[r + 1];

    float acc[8] = {0.f, 0.f, 0.f, 0.f, 0.f, 0.f, 0.f, 0.f};
    const size_t off = (size_t)hl * 8;

    int e = e0;
    for (; e + 4 <= e1; e += 4) {
        int2 d0 = g_edge[e],     d1 = g_edge[e + 1];
        int2 d2 = g_edge[e + 2], d3 = g_edge[e + 3];
        __half2 w0 = __float2half2_rn(__int_as_float(d0.y));
        __half2 w1 = __float2half2_rn(__int_as_float(d1.y));
        __half2 w2 = __float2half2_rn(__int_as_float(d2.y));
        __half2 w3 = __float2half2_rn(__int_as_float(d3.y));
        uint4 r0 = *(const uint4*)(H + (size_t)d0.x * F + off);
        uint4 r1 = *(const uint4*)(H + (size_t)d1.x * F + off);
        uint4 r2 = *(const uint4*)(H + (size_t)d2.x * F + off);
        uint4 r3 = *(const uint4*)(H + (size_t)d3.x * F + off);
        const __half2* h0 = (const __half2*)&r0;
        const __half2* h1 = (const __half2*)&r1;
        const __half2* h2 = (const __half2*)&r2;
        const __half2* h3 = (const __half2*)&r3;
        #pragma unroll
        for (int j = 0; j < 4; j++) {
            __half2 hacc = __hmul2(w0, h0[j]);
            hacc = __hfma2(w1, h1[j], hacc);
            hacc = __hfma2(w2, h2[j], hacc);
            hacc = __hfma2(w3, h3[j], hacc);
            float2 f = __half22float2(hacc);
            acc[j*2]   += f.x;
            acc[j*2+1] += f.y;
        }
    }
    for (; e < e1; e++) {
        int2 d = g_edge[e];
        float v = __int_as_float(d.y);
        uint4 rr = *(const uint4*)(H + (size_t)d.x * F + off);
        const __half2* hh = (const __half2*)&rr;
        #pragma unroll
        for (int j = 0; j < 4; j++) {
            float2 f = __half22float2(hh[j]);
            acc[j*2]   += v * f.x;
            acc[j*2+1] += v * f.y;
        }
    }
    uint4 o;
    __half2* op = (__half2*)&o;
    #pragma unroll
    for (int j = 0; j < 4; j++)
        op[j] = __floats2half2_rn(acc[j*2], acc[j*2+1]);
    *(uint4*)(out + (size_t)r * F + off) = o;
}

// ---------------- fused: row-restricted SPMM2 + linear + log_softmax ----------------
__global__ void __launch_bounds__(256, 6)
spmm2_final(const __half* __restrict__ H2, const float* __restrict__ b2,
            const float* __restrict__ s, const int* __restrict__ index,
            const float* __restrict__ Wl, const float* __restrict__ bl,
            float* __restrict__ out)
{
    __shared__ float Wls[(F + NSDIM) * NC];
    __shared__ float bls[NC];
    __shared__ float sin[16][F + NSDIM];

    for (int i = threadIdx.x; i < (F + NSDIM) * NC; i += blockDim.x) Wls[i] = Wl[i];
    if (threadIdx.x < NC) bls[threadIdx.x] = bl[threadIdx.x];
    __syncthreads();

    const int tid  = threadIdx.x;
    const int warp = tid >> 5;
    const int lane = tid & 31;
    const int half = lane >> 4;
    const int hl   = lane & 15;
    const int sidx = warp * 2 + half;
    int b = blockIdx.x * 16 + sidx;
    if (b >= BQ) return;

    int r = __ldg(index + b);
    int e0 = g_ptr[r];
    int e1 = g_ptr[r + 1];

    float acc[8] = {0.f, 0.f, 0.f, 0.f, 0.f, 0.f, 0.f, 0.f};
    const size_t off = (size_t)hl * 8;

    int e = e0;
    for (; e + 4 <= e1; e += 4) {
        int2 d0 = g_edge[e],     d1 = g_edge[e + 1];
        int2 d2 = g_edge[e + 2], d3 = g_edge[e + 3];
        __half2 w0 = __float2half2_rn(__int_as_float(d0.y));
        __half2 w1 = __float2half2_rn(__int_as_float(d1.y));
        __half2 w2 = __float2half2_rn(__int_as_float(d2.y));
        __half2 w3 = __float2half2_rn(__int_as_float(d3.y));
        uint4 r0 = *(const uint4*)(H2 + (size_t)d0.x * F + off);
        uint4 r1 = *(const uint4*)(H2 + (size_t)d1.x * F + off);
        uint4 r2 = *(const uint4*)(H2 + (size_t)d2.x * F + off);
        uint4 r3 = *(const uint4*)(H2 + (size_t)d3.x * F + off);
        const __half2* h0 = (const __half2*)&r0;
        const __half2* h1 = (const __half2*)&r1;
        const __half2* h2 = (const __half2*)&r2;
        const __half2* h3 = (const __half2*)&r3;
        #pragma unroll
        for (int j = 0; j < 4; j++) {
            __half2 hacc = __hmul2(w0, h0[j]);
            hacc = __hfma2(w1, h1[j], hacc);
            hacc = __hfma2(w2, h2[j], hacc);
            hacc = __hfma2(w3, h3[j], hacc);
            float2 f = __half22float2(hacc);
            acc[j*2]   += f.x;
            acc[j*2+1] += f.y;
        }
    }
    for (; e < e1; e++) {
        int2 d = g_edge[e];
        float v = __int_as_float(d.y);
        uint4 rr = *(const uint4*)(H2 + (size_t)d.x * F + off);
        const __half2* hh = (const __half2*)&rr;
        #pragma unroll
        for (int j = 0; j < 4; j++) {
            float2 f = __half22float2(hh[j]);
            acc[j*2]   += v * f.x;
            acc[j*2+1] += v * f.y;
        }
    }

    #pragma unroll
    for (int j = 0; j < 8; j++)
        sin[sidx][hl * 8 + j] = acc[j] + b2[hl * 8 + j];
    #pragma unroll
    for (int j = 0; j < 4; j++)
        sin[sidx][F + hl * 4 + j] = s[(size_t)b * NSDIM + hl * 4 + j];
    __syncwarp();

    float z = bls[hl];
    #pragma unroll 4
    for (int k = 0; k < F + NSDIM; k++)
        z += sin[sidx][k] * Wls[k * NC + hl];

    float m = z;
    #pragma unroll
    for (int o = 8; o > 0; o >>= 1)
        m = fmaxf(m, __shfl_xor_sync(0xffffffffu, m, o, 16));
    float ex = expf(z - m);
    float sum = ex;
    #pragma unroll
    for (int o = 8; o > 0; o >>= 1)
        sum += __shfl_xor_sync(0xffffffffu, sum, o, 16);
    out[(size_t)b * NC + hl] = z - m - logf(sum);
}

// ---------------- launch ----------------
extern "C" void kernel_launch(void* const* d_in, const int* in_sizes, int n_in,
                              void* d_out, int out_size)
{
    const float* s    = (const float*)d_in[0];
    const float* x    = (const float*)d_in[1];
    const int*   row  = (const int*)  d_in[2];
    const int*   col  = (const int*)  d_in[3];
    const float* val  = (const float*)d_in[4];
    const int*   index= (const int*)  d_in[5];
    const float* W1   = (const float*)d_in[6];
    const float* b1   = (const float*)d_in[7];
    const float* W2   = (const float*)d_in[8];
    const float* b2   = (const float*)d_in[9];
    const float* Wl   = (const float*)d_in[10];
    const float* bl   = (const float*)d_in[11];
    float* out = (float*)d_out;

    __half *A, *B, *Wh;
    void *csp;
    cudaGetSymbolAddress((void**)&A, g_bufA);
    cudaGetSymbolAddress((void**)&B, g_bufB);
    cudaGetSymbolAddress((void**)&Wh, g_Wh);
    cudaGetSymbolAddress(&csp, g_cs);

    static cudaStream_t side = nullptr;
    static cudaEvent_t evFork = nullptr, evSide = nullptr;
    if (side == nullptr) {
        cudaStreamCreateWithFlags(&side, cudaStreamNonBlocking);
        cudaEventCreateWithFlags(&evFork, cudaEventDisableTiming);
        cudaEventCreateWithFlags(&evSide, cudaEventDisableTiming);
        cudaFuncSetAttribute((const void*)gemm128_fp16<false, false>, cudaFuncAttributeMaxDynamicSharedMemorySize, GEMM_SMEM);
        cudaFuncSetAttribute((const void*)gemm128_fp16<true, true>,   cudaFuncAttributeMaxDynamicSharedMemorySize, GEMM_SMEM);
    }

    const int gemm_grid  = (NN + 127) / 128;           // 782
    const int edge_grid  = (NEDGE + 255) / 256;        // 6250
    const int spmm_grid  = (NN + 15) / 16;             // 6250

    // fork: CSR + C* build on side stream
    cudaEventRecord(evFork, 0);
    cudaStreamWaitEvent(side, evFork, 0);
    cudaMemsetAsync(csp, 0, sizeof(CsrScratch), side);
    flagidx_kernel<<<(BQ + 255) / 256, 256, 0, side>>>(index);
    histmark_kernel<<<edge_grid, 256, 0, side>>>(row, col, NEDGE);
    scan_compact<<<SCAN_NB, 256, 0, side>>>(NN, NEDGE);
    scatter_kernel<<<edge_grid, 256, 0, side>>>(row, col, val, NEDGE);
    cudaEventRecord(evSide, side);

    // main stream: W transpose, then GEMM1 (concurrent with side build)
    wtrans_kernel<<<128, 256>>>(W1, W2);
    gemm128_fp16<false, false><<<gemm_grid, 256, GEMM_SMEM>>>(x, Wh, nullptr, A, NN);

    // join, then the dependent chain (restricted to C*)
    cudaStreamWaitEvent(0, evSide, 0);
    spmm_csr<<<spmm_grid, 256>>>(A, B);
    gemm128_fp16<true, true><<<gemm_grid, 256, GEMM_SMEM>>>(B, Wh + F * F, b1, A, NN);
    spmm2_final<<<(BQ + 15) / 16, 256>>>(A, b2, s, index, Wl, bl, out);
}

// round 15
// speedup vs baseline: 1.1275x; 1.0492x over previous
#include <cuda_runtime.h>
#include <cuda_fp16.h>
#include <cstdint>
#include <math.h>

#define NN      100000
#define NEDGE   1600000
#define F       128
#define BQ      8192
#define NSDIM   64
#define NC      16
#define SCAN_NB ((NN + 1023) / 1024)   // 98

// ---------------- scratch (__device__ globals, allocation-free) ----------------
__device__ __half g_bufA[(size_t)NN * F];
__device__ __half g_bufB[(size_t)NN * F];
__device__ __half g_Wh[2][F * F];      // W1,W2 transposed [n][k], fp16

struct CsrScratch {              // zeroed with ONE memset per launch
    int cnt[NN];                 // edge histogram
    int iflag[NN];               // node is in index set
    int flag[NN];                // node is in C*
    int bsum[128];               // cnt scan block sums
    int lsum[128];               // flag scan block sums
    unsigned int ctr;            // grid barrier
    unsigned int pad[3];
};
__device__ CsrScratch g_cs;
__device__ int      g_ptr[NN + 1];
__device__ unsigned g_pmark[NN];   // ptr | (need << 31)
__device__ int      g_rank[NEDGE]; // within-row rank of each edge
__device__ int2     g_edge[NEDGE]; // packed (col, val-bits)
__device__ int      g_list[NN];    // compacted C* rows
__device__ int      g_nlist;       // |C*|

// fp16 GEMM smem: As2 [128 m][68] half2-as-u32, Ws2 [128 n][68] half2-as-u32
#define S2 68
#define GEMM_SMEM (2 * 128 * S2 * 4)   // 69632 B -> 2 blocks/SM

// ---------------- W transpose+convert ----------------
__global__ void wtrans_kernel(const float* __restrict__ W1, const float* __restrict__ W2)
{
    int idx = blockIdx.x * blockDim.x + threadIdx.x;   // 32768 total
    int w   = idx >> 14;
    int rem = idx & 16383;
    int k   = rem >> 7;
    int n   = rem & 127;
    const float* Wsrc = (w == 0) ? W1 : W2;
    g_Wh[w][n * F + k] = __float2half_rn(Wsrc[k * F + n]);
}

// ---------------- fp16 tensor-core GEMM ----------------
template <bool FUSE, bool LIST>
__global__ void gemm128_fp16(const void* __restrict__ Xv, const __half* __restrict__ Wh,
                             const float* __restrict__ bias, __half* __restrict__ C, int M)
{
    extern __shared__ unsigned int smu[];
    unsigned int* As2 = smu;             // [128][S2]
    unsigned int* Ws2 = smu + 128 * S2;  // [128][S2]

    const int tid  = threadIdx.x;
    const int wid  = tid >> 5;
    const int lane = tid & 31;
    const int gid  = lane >> 2;
    const int tig  = lane & 3;
    const int wm   = wid & 3;
    const int wn   = wid >> 2;
    const int m0   = blockIdx.x * 128;

    const int nl = LIST ? g_nlist : M;
    if (LIST && m0 >= nl) return;

    #pragma unroll
    for (int i = 0; i < 8; i++) {
        int idx = i * 256 + tid;
        int n = idx >> 4;
        int j = idx & 15;
        uint4 u = ((const uint4*)Wh)[idx];
        *(uint4*)(Ws2 + n * S2 + j * 4) = u;
    }

    if (FUSE) {
        const __half* Xh = (const __half*)Xv;
        #pragma unroll
        for (int i = 0; i < 8; i++) {
            int idx = i * 256 + tid;
            int m  = idx >> 4;
            int k8 = (idx & 15) << 3;
            int gm = m0 + m;
            bool valid = gm < nl;
            int src = (LIST && valid) ? g_list[gm] : gm;
            uint4 raw = make_uint4(0u, 0u, 0u, 0u);
            if (valid) raw = *(const uint4*)(Xh + (size_t)src * F + k8);
            const __half2* hp = (const __half2*)&raw;
            unsigned int o[4];
            #pragma unroll
            for (int j = 0; j < 4; j++) {
                float2 f = __half22float2(hp[j]);
                float2 bb = *(const float2*)(bias + k8 + j * 2);
                f.x = fmaxf(f.x + bb.x, 0.f);
                f.y = fmaxf(f.y + bb.y, 0.f);
                __half2 h = __floats2half2_rn(f.x, f.y);
                o[j] = *(unsigned int*)&h;
            }
            int base = m * S2 + (k8 >> 1);
            *(uint2*)(As2 + base)     = make_uint2(o[0], o[1]);
            *(uint2*)(As2 + base + 2) = make_uint2(o[2], o[3]);
        }
    } else {
        const float* Xf = (const float*)Xv;
        #pragma unroll
        for (int i = 0; i < 16; i++) {
            int idx = i * 256 + tid;
            int m  = idx >> 5;
            int k4 = (idx & 31) << 2;
            int gm = m0 + m;
            float4 v = make_float4(0.f, 0.f, 0.f, 0.f);
            if (gm < nl) v = *(const float4*)(Xf + (size_t)gm * F + k4);
            __half2 h0 = __floats2half2_rn(v.x, v.y);
            __half2 h1 = __floats2half2_rn(v.z, v.w);
            int base = m * S2 + (k4 >> 1);
            *(uint2*)(As2 + base) = make_uint2(*(unsigned int*)&h0, *(unsigned int*)&h1);
        }
    }
    __syncthreads();

    float acc[2][8][4];
    #pragma unroll
    for (int a = 0; a < 2; a++)
        #pragma unroll
        for (int b = 0; b < 8; b++)
            #pragma unroll
            for (int c = 0; c < 4; c++) acc[a][b][c] = 0.f;

    #pragma unroll
    for (int ks = 0; ks < 8; ks++) {
        const int k0h = ks * 8;
        unsigned int afr[2][4];
        #pragma unroll
        for (int mf = 0; mf < 2; mf++) {
            int rb = wm * 32 + mf * 16 + gid;
            afr[mf][0] = As2[rb * S2 + k0h + tig];
            afr[mf][1] = As2[(rb + 8) * S2 + k0h + tig];
            afr[mf][2] = As2[rb * S2 + k0h + 4 + tig];
            afr[mf][3] = As2[(rb + 8) * S2 + k0h + 4 + tig];
        }
        unsigned int bfr[8][2];
        #pragma unroll
        for (int nf = 0; nf < 8; nf++) {
            int nb = wn * 64 + nf * 8 + gid;
            bfr[nf][0] = Ws2[nb * S2 + k0h + tig];
            bfr[nf][1] = Ws2[nb * S2 + k0h + 4 + tig];
        }
        #pragma unroll
        for (int mf = 0; mf < 2; mf++)
            #pragma unroll
            for (int nf = 0; nf < 8; nf++) {
                asm volatile(
                    "mma.sync.aligned.m16n8k16.row.col.f32.f16.f16.f32 "
                    "{%0,%1,%2,%3}, {%4,%5,%6,%7}, {%8,%9}, {%0,%1,%2,%3};"
                    : "+f"(acc[mf][nf][0]), "+f"(acc[mf][nf][1]),
                      "+f"(acc[mf][nf][2]), "+f"(acc[mf][nf][3])
                    : "r"(afr[mf][0]), "r"(afr[mf][1]), "r"(afr[mf][2]), "r"(afr[mf][3]),
                      "r"(bfr[nf][0]), "r"(bfr[nf][1]));
            }
    }

    #pragma unroll
    for (int mf = 0; mf < 2; mf++) {
        int r0 = m0 + wm * 32 + mf * 16 + gid;
        bool v0 = r0 < nl;
        bool v1 = r0 + 8 < nl;
        int d0 = (LIST && v0) ? g_list[r0] : r0;
        int d1 = (LIST && v1) ? g_list[r0 + 8] : r0 + 8;
        #pragma unroll
        for (int nf = 0; nf < 8; nf++) {
            int ccol = wn * 64 + nf * 8 + tig * 2;
            if (v0)
                *(__half2*)(C + (size_t)d0 * F + ccol) =
                    __floats2half2_rn(acc[mf][nf][0], acc[mf][nf][1]);
            if (v1)
                *(__half2*)(C + (size_t)d1 * F + ccol) =
                    __floats2half2_rn(acc[mf][nf][2], acc[mf][nf][3]);
        }
    }
}

// ---------------- CSR + C* build kernels ----------------
__global__ void flagidx_kernel(const int* __restrict__ index)
{
    int b = blockIdx.x * blockDim.x + threadIdx.x;
    if (b < BQ) g_cs.iflag[index[b]] = 1;
}

// fused: histogram (returning per-edge rank) + C* mark
__global__ void histmark_kernel(const int* __restrict__ row, const int* __restrict__ col, int ne)
{
    int e = blockIdx.x * blockDim.x + threadIdx.x;
    if (e < ne) {
        int r = row[e];
        int rk = atomicAdd(&g_cs.cnt[r], 1);
        g_rank[e] = rk;
        if (g_cs.iflag[r]) g_cs.flag[col[e]] = 1;
    }
}

// fused dual scan (single grid barrier): cnt -> g_ptr/g_pmark, flag -> g_list/g_nlist
__global__ void scan_compact(int n, int ne)
{
    __shared__ int smc[256];
    __shared__ int smf[256];
    __shared__ int wsc[8];
    __shared__ int wsf[8];
    __shared__ int s_pc, s_pf;
    const int tid = threadIdx.x;
    const int bid = blockIdx.x;
    const int nb  = gridDim.x;
    const int base = bid * 1024 + tid * 4;

    int vc[4], vf[4], nd[4];
    #pragma unroll
    for (int i = 0; i < 4; i++) {
        bool ok = base + i < n;
        vc[i] = ok ? g_cs.cnt[base + i] : 0;
        vf[i] = ok ? g_cs.flag[base + i] : 0;
        nd[i] = ok ? (vf[i] | g_cs.iflag[base + i]) : 0;
    }
    int tc = vc[0] + vc[1] + vc[2] + vc[3];
    int tf = vf[0] + vf[1] + vf[2] + vf[3];
    smc[tid] = tc;
    smf[tid] = tf;
    __syncthreads();
    #pragma unroll
    for (int o = 1; o < 256; o <<= 1) {
        int t1 = (tid >= o) ? smc[tid - o] : 0;
        int t2 = (tid >= o) ? smf[tid - o] : 0;
        __syncthreads();
        smc[tid] += t1;
        smf[tid] += t2;
        __syncthreads();
    }

    // single grid barrier, both totals published first
    if (tid == 0) {
        ((volatile int*)g_cs.bsum)[bid] = smc[255];
        ((volatile int*)g_cs.lsum)[bid] = smf[255];
        __threadfence();
        atomicAdd(&g_cs.ctr, 1u);
        while (((volatile unsigned int*)&g_cs.ctr)[0] < (unsigned)nb) {}
        __threadfence();
    }
    __syncthreads();

    int pc = (tid < bid) ? ((volatile int*)g_cs.bsum)[tid] : 0;
    int pf = (tid < bid) ? ((volatile int*)g_cs.lsum)[tid] : 0;
    #pragma unroll
    for (int o = 16; o; o >>= 1) {
        pc += __shfl_xor_sync(0xffffffffu, pc, o);
        pf += __shfl_xor_sync(0xffffffffu, pf, o);
    }
    if ((tid & 31) == 0) { wsc[tid >> 5] = pc; wsf[tid >> 5] = pf; }
    __syncthreads();
    if (tid < 8) {
        int q1 = wsc[tid], q2 = wsf[tid];
        #pragma unroll
        for (int o = 4; o; o >>= 1) {
            q1 += __shfl_xor_sync(0xffu, q1, o);
            q2 += __shfl_xor_sync(0xffu, q2, o);
        }
        if (tid == 0) { s_pc = q1; s_pf = q2; }
    }
    __syncthreads();

    int runc = s_pc + smc[tid] - tc;
    int runf = s_pf + smf[tid] - tf;
    #pragma unroll
    for (int i = 0; i < 4; i++) {
        if (base + i < n) {
            g_ptr[base + i]   = runc;
            g_pmark[base + i] = (unsigned)runc | (nd[i] ? 0x80000000u : 0u);
            if (vf[i]) g_list[runf] = base + i;
        }
        runc += vc[i];
        runf += vf[i];
    }
    if (bid == nb - 1 && tid == 255) {
        g_ptr[n] = ne;
        g_nlist = runf;
    }
}

// atomic-free scatter: position = ptr[r] + rank[e]; single random read (pmark)
__global__ void scatter_kernel(const int* __restrict__ row, const int* __restrict__ col,
                               const float* __restrict__ val, int ne)
{
    int e = blockIdx.x * blockDim.x + threadIdx.x;
    if (e < ne) {
        int r = row[e];
        unsigned pm = g_pmark[r];
        if (pm & 0x80000000u) {
            int p = (int)(pm & 0x7fffffffu) + g_rank[e];
            g_edge[p] = make_int2(col[e], __float_as_int(val[e]));
        }
    }
}

// ---------------- SPMM1 over compacted C* rows (int2 edges) ----------------
__global__ void __launch_bounds__(256, 6)
spmm_csr(const __half* __restrict__ H, __half* __restrict__ out)
{
    const int tid  = threadIdx.x;
    const int warp = tid >> 5;
    const int lane = tid & 31;
    const int half = lane >> 4;
    const int hl   = lane & 15;
    int li = blockIdx.x * 16 + warp * 2 + half;
    if (li >= g_nlist) return;
    int r = g_list[li];

    int e0 = g_ptr[r];
    int e1 = g_ptr[r + 1];

    float acc[8] = {0.f, 0.f, 0.f, 0.f, 0.f, 0.f, 0.f, 0.f};
    const size_t off = (size_t)hl * 8;

    int e = e0;
    for (; e + 4 <= e1; e += 4) {
        int2 d0 = g_edge[e],     d1 = g_edge[e + 1];
        int2 d2 = g_edge[e + 2], d3 = g_edge[e + 3];
        __half2 w0 = __float2half2_rn(__int_as_float(d0.y));
        __half2 w1 = __float2half2_rn(__int_as_float(d1.y));
        __half2 w2 = __float2half2_rn(__int_as_float(d2.y));
        __half2 w3 = __float2half2_rn(__int_as_float(d3.y));
        uint4 r0 = *(const uint4*)(H + (size_t)d0.x * F + off);
        uint4 r1 = *(const uint4*)(H + (size_t)d1.x * F + off);
        uint4 r2 = *(const uint4*)(H + (size_t)d2.x * F + off);
        uint4 r3 = *(const uint4*)(H + (size_t)d3.x * F + off);
        const __half2* h0 = (const __half2*)&r0;
        const __half2* h1 = (const __half2*)&r1;
        const __half2* h2 = (const __half2*)&r2;
        const __half2* h3 = (const __half2*)&r3;
        #pragma unroll
        for (int j = 0; j < 4; j++) {
            __half2 hacc = __hmul2(w0, h0[j]);
            hacc = __hfma2(w1, h1[j], hacc);
            hacc = __hfma2(w2, h2[j], hacc);
            hacc = __hfma2(w3, h3[j], hacc);
            float2 f = __half22float2(hacc);
            acc[j*2]   += f.x;
            acc[j*2+1] += f.y;
        }
    }
    for (; e < e1; e++) {
        int2 d = g_edge[e];
        float v = __int_as_float(d.y);
        uint4 rr = *(const uint4*)(H + (size_t)d.x * F + off);
        const __half2* hh = (const __half2*)&rr;
        #pragma unroll
        for (int j = 0; j < 4; j++) {
            float2 f = __half22float2(hh[j]);
            acc[j*2]   += v * f.x;
            acc[j*2+1] += v * f.y;
        }
    }
    uint4 o;
    __half2* op = (__half2*)&o;
    #pragma unroll
    for (int j = 0; j < 4; j++)
        op[j] = __floats2half2_rn(acc[j*2], acc[j*2+1]);
    *(uint4*)(out + (size_t)r * F + off) = o;
}

// ---------------- fused: row-restricted SPMM2 + linear + log_softmax ----------------
__global__ void __launch_bounds__(256, 6)
spmm2_final(const __half* __restrict__ H2, const float* __restrict__ b2,
            const float* __restrict__ s, const int* __restrict__ index,
            const float* __restrict__ Wl, const float* __restrict__ bl,
            float* __restrict__ out)
{
    __shared__ float Wls[(F + NSDIM) * NC];
    __shared__ float bls[NC];
    __shared__ float sin[16][F + NSDIM];

    for (int i = threadIdx.x; i < (F + NSDIM) * NC; i += blockDim.x) Wls[i] = Wl[i];
    if (threadIdx.x < NC) bls[threadIdx.x] = bl[threadIdx.x];
    __syncthreads();

    const int tid  = threadIdx.x;
    const int warp = tid >> 5;
    const int lane = tid & 31;
    const int half = lane >> 4;
    const int hl   = lane & 15;
    const int sidx = warp * 2 + half;
    int b = blockIdx.x * 16 + sidx;
    if (b >= BQ) return;

    int r = __ldg(index + b);
    int e0 = g_ptr[r];
    int e1 = g_ptr[r + 1];

    float acc[8] = {0.f, 0.f, 0.f, 0.f, 0.f, 0.f, 0.f, 0.f};
    const size_t off = (size_t)hl * 8;

    int e = e0;
    for (; e + 4 <= e1; e += 4) {
        int2 d0 = g_edge[e],     d1 = g_edge[e + 1];
        int2 d2 = g_edge[e + 2], d3 = g_edge[e + 3];
        __half2 w0 = __float2half2_rn(__int_as_float(d0.y));
        __half2 w1 = __float2half2_rn(__int_as_float(d1.y));
        __half2 w2 = __float2half2_rn(__int_as_float(d2.y));
        __half2 w3 = __float2half2_rn(__int_as_float(d3.y));
        uint4 r0 = *(const uint4*)(H2 + (size_t)d0.x * F + off);
        uint4 r1 = *(const uint4*)(H2 + (size_t)d1.x * F + off);
        uint4 r2 = *(const uint4*)(H2 + (size_t)d2.x * F + off);
        uint4 r3 = *(const uint4*)(H2 + (size_t)d3.x * F + off);
        const __half2* h0 = (const __half2*)&r0;
        const __half2* h1 = (const __half2*)&r1;
        const __half2* h2 = (const __half2*)&r2;
        const __half2* h3 = (const __half2*)&r3;
        #pragma unroll
        for (int j = 0; j < 4; j++) {
            __half2 hacc = __hmul2(w0, h0[j]);
            hacc = __hfma2(w1, h1[j], hacc);
            hacc = __hfma2(w2, h2[j], hacc);
            hacc = __hfma2(w3, h3[j], hacc);
            float2 f = __half22float2(hacc);
            acc[j*2]   += f.x;
            acc[j*2+1] += f.y;
        }
    }
    for (; e < e1; e++) {
        int2 d = g_edge[e];
        float v = __int_as_float(d.y);
        uint4 rr = *(const uint4*)(H2 + (size_t)d.x * F + off);
        const __half2* hh = (const __half2*)&rr;
        #pragma unroll
        for (int j = 0; j < 4; j++) {
            float2 f = __half22float2(hh[j]);
            acc[j*2]   += v * f.x;
            acc[j*2+1] += v * f.y;
        }
    }

    #pragma unroll
    for (int j = 0; j < 8; j++)
        sin[sidx][hl * 8 + j] = acc[j] + b2[hl * 8 + j];
    #pragma unroll
    for (int j = 0; j < 4; j++)
        sin[sidx][F + hl * 4 + j] = s[(size_t)b * NSDIM + hl * 4 + j];
    __syncwarp();

    float z = bls[hl];
    #pragma unroll 4
    for (int k = 0; k < F + NSDIM; k++)
        z += sin[sidx][k] * Wls[k * NC + hl];

    float m = z;
    #pragma unroll
    for (int o = 8; o > 0; o >>= 1)
        m = fmaxf(m, __shfl_xor_sync(0xffffffffu, m, o, 16));
    float ex = expf(z - m);
    float sum = ex;
    #pragma unroll
    for (int o = 8; o > 0; o >>= 1)
        sum += __shfl_xor_sync(0xffffffffu, sum, o, 16);
    out[(size_t)b * NC + hl] = z - m - logf(sum);
}

// ---------------- launch ----------------
extern "C" void kernel_launch(void* const* d_in, const int* in_sizes, int n_in,
                              void* d_out, int out_size)
{
    const float* s    = (const float*)d_in[0];
    const float* x    = (const float*)d_in[1];
    const int*   row  = (const int*)  d_in[2];
    const int*   col  = (const int*)  d_in[3];
    const float* val  = (const float*)d_in[4];
    const int*   index= (const int*)  d_in[5];
    const float* W1   = (const float*)d_in[6];
    const float* b1   = (const float*)d_in[7];
    const float* W2   = (const float*)d_in[8];
    const float* b2   = (const float*)d_in[9];
    const float* Wl   = (const float*)d_in[10];
    const float* bl   = (const float*)d_in[11];
    float* out = (float*)d_out;

    __half *A, *B, *Wh;
    void *csp;
    cudaGetSymbolAddress((void**)&A, g_bufA);
    cudaGetSymbolAddress((void**)&B, g_bufB);
    cudaGetSymbolAddress((void**)&Wh, g_Wh);
    cudaGetSymbolAddress(&csp, g_cs);

    static cudaStream_t side = nullptr;
    static cudaEvent_t evFork = nullptr, evSide = nullptr;
    if (side == nullptr) {
        cudaStreamCreateWithFlags(&side, cudaStreamNonBlocking);
        cudaEventCreateWithFlags(&evFork, cudaEventDisableTiming);
        cudaEventCreateWithFlags(&evSide, cudaEventDisableTiming);
        cudaFuncSetAttribute((const void*)gemm128_fp16<false, false>, cudaFuncAttributeMaxDynamicSharedMemorySize, GEMM_SMEM);
        cudaFuncSetAttribute((const void*)gemm128_fp16<true, true>,   cudaFuncAttributeMaxDynamicSharedMemorySize, GEMM_SMEM);
    }

    const int gemm_grid  = (NN + 127) / 128;           // 782
    const int edge_grid  = (NEDGE + 255) / 256;        // 6250
    const int spmm_grid  = (NN + 15) / 16;             // 6250

    // fork: CSR + C* build on side stream
    cudaEventRecord(evFork, 0);
    cudaStreamWaitEvent(side, evFork, 0);
    cudaMemsetAsync(csp, 0, sizeof(CsrScratch), side);
    flagidx_kernel<<<(BQ + 255) / 256, 256, 0, side>>>(index);
    histmark_kernel<<<edge_grid, 256, 0, side>>>(row, col, NEDGE);
    scan_compact<<<SCAN_NB, 256, 0, side>>>(NN, NEDGE);
    scatter_kernel<<<edge_grid, 256, 0, side>>>(row, col, val, NEDGE);
    cudaEventRecord(evSide, side);

    // main stream: W transpose, then GEMM1 (concurrent with side build)
    wtrans_kernel<<<128, 256>>>(W1, W2);
    gemm128_fp16<false, false><<<gemm_grid, 256, GEMM_SMEM>>>(x, Wh, nullptr, A, NN);

    // join, then the dependent chain (restricted to C*)
    cudaStreamWaitEvent(0, evSide, 0);
    spmm_csr<<<spmm_grid, 256>>>(A, B);
    gemm128_fp16<true, true><<<gemm_grid, 256, GEMM_SMEM>>>(B, Wh + F * F, b1, A, NN);
    spmm2_final<<<(BQ + 15) / 16, 256>>>(A, b2, s, index, Wl, bl, out);
}

// round 16
// speedup vs baseline: 1.1364x; 1.0079x over previous
#include <cuda_runtime.h>
#include <cuda_fp16.h>
#include <cstdint>
#include <math.h>

#define NN      100000
#define NEDGE   1600000
#define F       128
#define BQ      8192
#define NSDIM   64
#define NC      16
#define SCAN_NB ((NN + 1023) / 1024)   // 98
#define ESPLIT  1152000                // ~72% of NEDGE on side stream

// ---------------- scratch (__device__ globals, allocation-free) ----------------
__device__ __half g_bufA[(size_t)NN * F];
__device__ __half g_bufB[(size_t)NN * F];
__device__ __half g_Wh[2][F * F];      // W1,W2 transposed [n][k], fp16

struct CsrScratch {              // zeroed with ONE memset per launch
    int cnt[NN];                 // edge histogram
    int iflag[NN];               // node is in index set
    int flag[NN];                // node is in C*
    int bsum[128];               // cnt scan block sums
    int lsum[128];               // flag scan block sums
    unsigned int ctr;            // grid barrier
    unsigned int pad[3];
};
__device__ CsrScratch g_cs;
__device__ int      g_ptr[NN + 1];
__device__ unsigned g_pmark[NN];   // ptr | (need << 31)
__device__ int      g_rank[NEDGE]; // within-row rank of each edge
__device__ int2     g_edge[NEDGE]; // packed (col, val-bits)
__device__ int      g_list[NN];    // compacted C* rows
__device__ int      g_nlist;       // |C*|

// fp16 GEMM smem: As2 [128 m][68] half2-as-u32, Ws2 [128 n][68] half2-as-u32
#define S2 68
#define GEMM_SMEM (2 * 128 * S2 * 4)   // 69632 B -> 2 blocks/SM

// ---------------- W transpose+convert ----------------
__global__ void wtrans_kernel(const float* __restrict__ W1, const float* __restrict__ W2)
{
    int idx = blockIdx.x * blockDim.x + threadIdx.x;   // 32768 total
    int w   = idx >> 14;
    int rem = idx & 16383;
    int k   = rem >> 7;
    int n   = rem & 127;
    const float* Wsrc = (w == 0) ? W1 : W2;
    g_Wh[w][n * F + k] = __float2half_rn(Wsrc[k * F + n]);
}

// ---------------- fp16 tensor-core GEMM ----------------
template <bool FUSE, bool LIST>
__global__ void gemm128_fp16(const void* __restrict__ Xv, const __half* __restrict__ Wh,
                             const float* __restrict__ bias, __half* __restrict__ C, int M)
{
    extern __shared__ unsigned int smu[];
    unsigned int* As2 = smu;             // [128][S2]
    unsigned int* Ws2 = smu + 128 * S2;  // [128][S2]

    const int tid  = threadIdx.x;
    const int wid  = tid >> 5;
    const int lane = tid & 31;
    const int gid  = lane >> 2;
    const int tig  = lane & 3;
    const int wm   = wid & 3;
    const int wn   = wid >> 2;
    const int m0   = blockIdx.x * 128;

    const int nl = LIST ? g_nlist : M;
    if (LIST && m0 >= nl) return;

    #pragma unroll
    for (int i = 0; i < 8; i++) {
        int idx = i * 256 + tid;
        int n = idx >> 4;
        int j = idx & 15;
        uint4 u = ((const uint4*)Wh)[idx];
        *(uint4*)(Ws2 + n * S2 + j * 4) = u;
    }

    if (FUSE) {
        const __half* Xh = (const __half*)Xv;
        #pragma unroll
        for (int i = 0; i < 8; i++) {
            int idx = i * 256 + tid;
            int m  = idx >> 4;
            int k8 = (idx & 15) << 3;
            int gm = m0 + m;
            bool valid = gm < nl;
            int src = (LIST && valid) ? g_list[gm] : gm;
            uint4 raw = make_uint4(0u, 0u, 0u, 0u);
            if (valid) raw = *(const uint4*)(Xh + (size_t)src * F + k8);
            const __half2* hp = (const __half2*)&raw;
            unsigned int o[4];
            #pragma unroll
            for (int j = 0; j < 4; j++) {
                float2 f = __half22float2(hp[j]);
                float2 bb = *(const float2*)(bias + k8 + j * 2);
                f.x = fmaxf(f.x + bb.x, 0.f);
                f.y = fmaxf(f.y + bb.y, 0.f);
                __half2 h = __floats2half2_rn(f.x, f.y);
                o[j] = *(unsigned int*)&h;
            }
            int base = m * S2 + (k8 >> 1);
            *(uint2*)(As2 + base)     = make_uint2(o[0], o[1]);
            *(uint2*)(As2 + base + 2) = make_uint2(o[2], o[3]);
        }
    } else {
        const float* Xf = (const float*)Xv;
        #pragma unroll
        for (int i = 0; i < 16; i++) {
            int idx = i * 256 + tid;
            int m  = idx >> 5;
            int k4 = (idx & 31) << 2;
            int gm = m0 + m;
            float4 v = make_float4(0.f, 0.f, 0.f, 0.f);
            if (gm < nl) v = *(const float4*)(Xf + (size_t)gm * F + k4);
            __half2 h0 = __floats2half2_rn(v.x, v.y);
            __half2 h1 = __floats2half2_rn(v.z, v.w);
            int base = m * S2 + (k4 >> 1);
            *(uint2*)(As2 + base) = make_uint2(*(unsigned int*)&h0, *(unsigned int*)&h1);
        }
    }
    __syncthreads();

    float acc[2][8][4];
    #pragma unroll
    for (int a = 0; a < 2; a++)
        #pragma unroll
        for (int b = 0; b < 8; b++)
            #pragma unroll
            for (int c = 0; c < 4; c++) acc[a][b][c] = 0.f;

    #pragma unroll
    for (int ks = 0; ks < 8; ks++) {
        const int k0h = ks * 8;
        unsigned int afr[2][4];
        #pragma unroll
        for (int mf = 0; mf < 2; mf++) {
            int rb = wm * 32 + mf * 16 + gid;
            afr[mf][0] = As2[rb * S2 + k0h + tig];
            afr[mf][1] = As2[(rb + 8) * S2 + k0h + tig];
            afr[mf][2] = As2[rb * S2 + k0h + 4 + tig];
            afr[mf][3] = As2[(rb + 8) * S2 + k0h + 4 + tig];
        }
        unsigned int bfr[8][2];
        #pragma unroll
        for (int nf = 0; nf < 8; nf++) {
            int nb = wn * 64 + nf * 8 + gid;
            bfr[nf][0] = Ws2[nb * S2 + k0h + tig];
            bfr[nf][1] = Ws2[nb * S2 + k0h + 4 + tig];
        }
        #pragma unroll
        for (int mf = 0; mf < 2; mf++)
            #pragma unroll
            for (int nf = 0; nf < 8; nf++) {
                asm volatile(
                    "mma.sync.aligned.m16n8k16.row.col.f32.f16.f16.f32 "
                    "{%0,%1,%2,%3}, {%4,%5,%6,%7}, {%8,%9}, {%0,%1,%2,%3};"
                    : "+f"(acc[mf][nf][0]), "+f"(acc[mf][nf][1]),
                      "+f"(acc[mf][nf][2]), "+f"(acc[mf][nf][3])
                    : "r"(afr[mf][0]), "r"(afr[mf][1]), "r"(afr[mf][2]), "r"(afr[mf][3]),
                      "r"(bfr[nf][0]), "r"(bfr[nf][1]));
            }
    }

    #pragma unroll
    for (int mf = 0; mf < 2; mf++) {
        int r0 = m0 + wm * 32 + mf * 16 + gid;
        bool v0 = r0 < nl;
        bool v1 = r0 + 8 < nl;
        int d0 = (LIST && v0) ? g_list[r0] : r0;
        int d1 = (LIST && v1) ? g_list[r0 + 8] : r0 + 8;
        #pragma unroll
        for (int nf = 0; nf < 8; nf++) {
            int ccol = wn * 64 + nf * 8 + tig * 2;
            if (v0)
                *(__half2*)(C + (size_t)d0 * F + ccol) =
                    __floats2half2_rn(acc[mf][nf][0], acc[mf][nf][1]);
            if (v1)
                *(__half2*)(C + (size_t)d1 * F + ccol) =
                    __floats2half2_rn(acc[mf][nf][2], acc[mf][nf][3]);
        }
    }
}

// ---------------- CSR + C* build kernels ----------------
__global__ void flagidx_kernel(const int* __restrict__ index)
{
    int b = blockIdx.x * blockDim.x + threadIdx.x;
    if (b < BQ) g_cs.iflag[index[b]] = 1;
}

// fused: histogram (returning per-edge rank) + C* mark
__global__ void histmark_kernel(const int* __restrict__ row, const int* __restrict__ col, int ne)
{
    int e = blockIdx.x * blockDim.x + threadIdx.x;
    if (e < ne) {
        int r = row[e];
        int rk = atomicAdd(&g_cs.cnt[r], 1);
        g_rank[e] = rk;
        if (g_cs.iflag[r]) g_cs.flag[col[e]] = 1;
    }
}

// fused dual scan (single grid barrier): cnt -> g_ptr/g_pmark, flag -> g_list/g_nlist
__global__ void scan_compact(int n, int ne)
{
    __shared__ int smc[256];
    __shared__ int smf[256];
    __shared__ int wsc[8];
    __shared__ int wsf[8];
    __shared__ int s_pc, s_pf;
    const int tid = threadIdx.x;
    const int bid = blockIdx.x;
    const int nb  = gridDim.x;
    const int base = bid * 1024 + tid * 4;

    int vc[4], vf[4], nd[4];
    #pragma unroll
    for (int i = 0; i < 4; i++) {
        bool ok = base + i < n;
        vc[i] = ok ? g_cs.cnt[base + i] : 0;
        vf[i] = ok ? g_cs.flag[base + i] : 0;
        nd[i] = ok ? (vf[i] | g_cs.iflag[base + i]) : 0;
    }
    int tc = vc[0] + vc[1] + vc[2] + vc[3];
    int tf = vf[0] + vf[1] + vf[2] + vf[3];
    smc[tid] = tc;
    smf[tid] = tf;
    __syncthreads();
    #pragma unroll
    for (int o = 1; o < 256; o <<= 1) {
        int t1 = (tid >= o) ? smc[tid - o] : 0;
        int t2 = (tid >= o) ? smf[tid - o] : 0;
        __syncthreads();
        smc[tid] += t1;
        smf[tid] += t2;
        __syncthreads();
    }

    if (tid == 0) {
        ((volatile int*)g_cs.bsum)[bid] = smc[255];
        ((volatile int*)g_cs.lsum)[bid] = smf[255];
        __threadfence();
        atomicAdd(&g_cs.ctr, 1u);
        while (((volatile unsigned int*)&g_cs.ctr)[0] < (unsigned)nb) {}
        __threadfence();
    }
    __syncthreads();

    int pc = (tid < bid) ? ((volatile int*)g_cs.bsum)[tid] : 0;
    int pf = (tid < bid) ? ((volatile int*)g_cs.lsum)[tid] : 0;
    #pragma unroll
    for (int o = 16; o; o >>= 1) {
        pc += __shfl_xor_sync(0xffffffffu, pc, o);
        pf += __shfl_xor_sync(0xffffffffu, pf, o);
    }
    if ((tid & 31) == 0) { wsc[tid >> 5] = pc; wsf[tid >> 5] = pf; }
    __syncthreads();
    if (tid < 8) {
        int q1 = wsc[tid], q2 = wsf[tid];
        #pragma unroll
        for (int o = 4; o; o >>= 1) {
            q1 += __shfl_xor_sync(0xffu, q1, o);
            q2 += __shfl_xor_sync(0xffu, q2, o);
        }
        if (tid == 0) { s_pc = q1; s_pf = q2; }
    }
    __syncthreads();

    int runc = s_pc + smc[tid] - tc;
    int runf = s_pf + smf[tid] - tf;
    #pragma unroll
    for (int i = 0; i < 4; i++) {
        if (base + i < n) {
            g_ptr[base + i]   = runc;
            g_pmark[base + i] = (unsigned)runc | (nd[i] ? 0x80000000u : 0u);
            if (vf[i]) g_list[runf] = base + i;
        }
        runc += vc[i];
        runf += vf[i];
    }
    if (bid == nb - 1 && tid == 255) {
        g_ptr[n] = ne;
        g_nlist = runf;
    }
}

// atomic-free scatter over an edge range [e0, e1)
__global__ void scatter_kernel(const int* __restrict__ row, const int* __restrict__ col,
                               const float* __restrict__ val, int e0, int e1)
{
    int e = e0 + blockIdx.x * blockDim.x + threadIdx.x;
    if (e < e1) {
        int r = row[e];
        unsigned pm = g_pmark[r];
        if (pm & 0x80000000u) {
            int p = (int)(pm & 0x7fffffffu) + g_rank[e];
            g_edge[p] = make_int2(col[e], __float_as_int(val[e]));
        }
    }
}

// ---------------- SPMM1 over compacted C* rows (int2 edges) ----------------
__global__ void __launch_bounds__(256, 6)
spmm_csr(const __half* __restrict__ H, __half* __restrict__ out)
{
    const int tid  = threadIdx.x;
    const int warp = tid >> 5;
    const int lane = tid & 31;
    const int half = lane >> 4;
    const int hl   = lane & 15;
    int li = blockIdx.x * 16 + warp * 2 + half;
    if (li >= g_nlist) return;
    int r = g_list[li];

    int e0 = g_ptr[r];
    int e1 = g_ptr[r + 1];

    float acc[8] = {0.f, 0.f, 0.f, 0.f, 0.f, 0.f, 0.f, 0.f};
    const size_t off = (size_t)hl * 8;

    int e = e0;
    for (; e + 4 <= e1; e += 4) {
        int2 d0 = g_edge[e],     d1 = g_edge[e + 1];
        int2 d2 = g_edge[e + 2], d3 = g_edge[e + 3];
        __half2 w0 = __float2half2_rn(__int_as_float(d0.y));
        __half2 w1 = __float2half2_rn(__int_as_float(d1.y));
        __half2 w2 = __float2half2_rn(__int_as_float(d2.y));
        __half2 w3 = __float2half2_rn(__int_as_float(d3.y));
        uint4 r0 = *(const uint4*)(H + (size_t)d0.x * F + off);
        uint4 r1 = *(const uint4*)(H + (size_t)d1.x * F + off);
        uint4 r2 = *(const uint4*)(H + (size_t)d2.x * F + off);
        uint4 r3 = *(const uint4*)(H + (size_t)d3.x * F + off);
        const __half2* h0 = (const __half2*)&r0;
        const __half2* h1 = (const __half2*)&r1;
        const __half2* h2 = (const __half2*)&r2;
        const __half2* h3 = (const __half2*)&r3;
        #pragma unroll
        for (int j = 0; j < 4; j++) {
            __half2 hacc = __hmul2(w0, h0[j]);
            hacc = __hfma2(w1, h1[j], hacc);
            hacc = __hfma2(w2, h2[j], hacc);
            hacc = __hfma2(w3, h3[j], hacc);
            float2 f = __half22float2(hacc);
            acc[j*2]   += f.x;
            acc[j*2+1] += f.y;
        }
    }
    for (; e < e1; e++) {
        int2 d = g_edge[e];
        float v = __int_as_float(d.y);
        uint4 rr = *(const uint4*)(H + (size_t)d.x * F + off);
        const __half2* hh = (const __half2*)&rr;
        #pragma unroll
        for (int j = 0; j < 4; j++) {
            float2 f = __half22float2(hh[j]);
            acc[j*2]   += v * f.x;
            acc[j*2+1] += v * f.y;
        }
    }
    uint4 o;
    __half2* op = (__half2*)&o;
    #pragma unroll
    for (int j = 0; j < 4; j++)
        op[j] = __floats2half2_rn(acc[j*2], acc[j*2+1]);
    *(uint4*)(out + (size_t)r * F + off) = o;
}

// ---------------- fused: row-restricted SPMM2 + linear + log_softmax ----------------
__global__ void __launch_bounds__(256, 6)
spmm2_final(const __half* __restrict__ H2, const float* __restrict__ b2,
            const float* __restrict__ s, const int* __restrict__ index,
            const float* __restrict__ Wl, const float* __restrict__ bl,
            float* __restrict__ out)
{
    __shared__ float Wls[(F + NSDIM) * NC];
    __shared__ float bls[NC];
    __shared__ float sin[16][F + NSDIM];

    for (int i = threadIdx.x; i < (F + NSDIM) * NC; i += blockDim.x) Wls[i] = Wl[i];
    if (threadIdx.x < NC) bls[threadIdx.x] = bl[threadIdx.x];
    __syncthreads();

    const int tid  = threadIdx.x;
    const int warp = tid >> 5;
    const int lane = tid & 31;
    const int half = lane >> 4;
    const int hl   = lane & 15;
    const int sidx = warp * 2 + half;
    int b = blockIdx.x * 16 + sidx;
    if (b >= BQ) return;

    int r = __ldg(index + b);
    int e0 = g_ptr[r];
    int e1 = g_ptr[r + 1];

    float acc[8] = {0.f, 0.f, 0.f, 0.f, 0.f, 0.f, 0.f, 0.f};
    const size_t off = (size_t)hl * 8;

    int e = e0;
    for (; e + 4 <= e1; e += 4) {
        int2 d0 = g_edge[e],     d1 = g_edge[e + 1];
        int2 d2 = g_edge[e + 2], d3 = g_edge[e + 3];
        __half2 w0 = __float2half2_rn(__int_as_float(d0.y));
        __half2 w1 = __float2half2_rn(__int_as_float(d1.y));
        __half2 w2 = __float2half2_rn(__int_as_float(d2.y));
        __half2 w3 = __float2half2_rn(__int_as_float(d3.y));
        uint4 r0 = *(const uint4*)(H2 + (size_t)d0.x * F + off);
        uint4 r1 = *(const uint4*)(H2 + (size_t)d1.x * F + off);
        uint4 r2 = *(const uint4*)(H2 + (size_t)d2.x * F + off);
        uint4 r3 = *(const uint4*)(H2 + (size_t)d3.x * F + off);
        const __half2* h0 = (const __half2*)&r0;
        const __half2* h1 = (const __half2*)&r1;
        const __half2* h2 = (const __half2*)&r2;
        const __half2* h3 = (const __half2*)&r3;
        #pragma unroll
        for (int j = 0; j < 4; j++) {
            __half2 hacc = __hmul2(w0, h0[j]);
            hacc = __hfma2(w1, h1[j], hacc);
            hacc = __hfma2(w2, h2[j], hacc);
            hacc = __hfma2(w3, h3[j], hacc);
            float2 f = __half22float2(hacc);
            acc[j*2]   += f.x;
            acc[j*2+1] += f.y;
        }
    }
    for (; e < e1; e++) {
        int2 d = g_edge[e];
        float v = __int_as_float(d.y);
        uint4 rr = *(const uint4*)(H2 + (size_t)d.x * F + off);
        const __half2* hh = (const __half2*)&rr;
        #pragma unroll
        for (int j = 0; j < 4; j++) {
            float2 f = __half22float2(hh[j]);
            acc[j*2]   += v * f.x;
            acc[j*2+1] += v * f.y;
        }
    }

    #pragma unroll
    for (int j = 0; j < 8; j++)
        sin[sidx][hl * 8 + j] = acc[j] + b2[hl * 8 + j];
    #pragma unroll
    for (int j = 0; j < 4; j++)
        sin[sidx][F + hl * 4 + j] = s[(size_t)b * NSDIM + hl * 4 + j];
    __syncwarp();

    float z = bls[hl];
    #pragma unroll 4
    for (int k = 0; k < F + NSDIM; k++)
        z += sin[sidx][k] * Wls[k * NC + hl];

    float m = z;
    #pragma unroll
    for (int o = 8; o > 0; o >>= 1)
        m = fmaxf(m, __shfl_xor_sync(0xffffffffu, m, o, 16));
    float ex = expf(z - m);
    float sum = ex;
    #pragma unroll
    for (int o = 8; o > 0; o >>= 1)
        sum += __shfl_xor_sync(0xffffffffu, sum, o, 16);
    out[(size_t)b * NC + hl] = z - m - logf(sum);
}

// ---------------- launch ----------------
extern "C" void kernel_launch(void* const* d_in, const int* in_sizes, int n_in,
                              void* d_out, int out_size)
{
    const float* s    = (const float*)d_in[0];
    const float* x    = (const float*)d_in[1];
    const int*   row  = (const int*)  d_in[2];
    const int*   col  = (const int*)  d_in[3];
    const float* val  = (const float*)d_in[4];
    const int*   index= (const int*)  d_in[5];
    const float* W1   = (const float*)d_in[6];
    const float* b1   = (const float*)d_in[7];
    const float* W2   = (const float*)d_in[8];
    const float* b2   = (const float*)d_in[9];
    const float* Wl   = (const float*)d_in[10];
    const float* bl   = (const float*)d_in[11];
    float* out = (float*)d_out;

    __half *A, *B, *Wh;
    void *csp;
    cudaGetSymbolAddress((void**)&A, g_bufA);
    cudaGetSymbolAddress((void**)&B, g_bufB);
    cudaGetSymbolAddress((void**)&Wh, g_Wh);
    cudaGetSymbolAddress(&csp, g_cs);

    static cudaStream_t side = nullptr;
    static cudaEvent_t evFork = nullptr, evScan = nullptr, evSide = nullptr;
    if (side == nullptr) {
        cudaStreamCreateWithFlags(&side, cudaStreamNonBlocking);
        cudaEventCreateWithFlags(&evFork, cudaEventDisableTiming);
        cudaEventCreateWithFlags(&evScan, cudaEventDisableTiming);
        cudaEventCreateWithFlags(&evSide, cudaEventDisableTiming);
        cudaFuncSetAttribute((const void*)gemm128_fp16<false, false>, cudaFuncAttributeMaxDynamicSharedMemorySize, GEMM_SMEM);
        cudaFuncSetAttribute((const void*)gemm128_fp16<true, true>,   cudaFuncAttributeMaxDynamicSharedMemorySize, GEMM_SMEM);
    }

    const int gemm_grid  = (NN + 127) / 128;           // 782
    const int edge_grid  = (NEDGE + 255) / 256;        // 6250

    // fork: CSR + C* build on side stream; scatter split [0,ESPLIT) on side
    cudaEventRecord(evFork, 0);
    cudaStreamWaitEvent(side, evFork, 0);
    cudaMemsetAsync(csp, 0, sizeof(CsrScratch), side);
    flagidx_kernel<<<(BQ + 255) / 256, 256, 0, side>>>(index);
    histmark_kernel<<<edge_grid, 256, 0, side>>>(row, col, NEDGE);
    scan_compact<<<SCAN_NB, 256, 0, side>>>(NN, NEDGE);
    cudaEventRecord(evScan, side);
    scatter_kernel<<<(ESPLIT + 255) / 256, 256, 0, side>>>(row, col, val, 0, ESPLIT);
    cudaEventRecord(evSide, side);

    // main stream: W transpose, GEMM1 (concurrent with side build),
    // then the tail of the scatter [ESPLIT, NEDGE) once scan is done
    wtrans_kernel<<<128, 256>>>(W1, W2);
    gemm128_fp16<false, false><<<gemm_grid, 256, GEMM_SMEM>>>(x, Wh, nullptr, A, NN);
    cudaStreamWaitEvent(0, evScan, 0);
    scatter_kernel<<<(NEDGE - ESPLIT + 255) / 256, 256>>>(row, col, val, ESPLIT, NEDGE);

    // join, then the dependent chain (restricted to C*)
    cudaStreamWaitEvent(0, evSide, 0);
    spmm_csr<<<(NN + 15) / 16, 256>>>(A, B);
    gemm128_fp16<true, true><<<gemm_grid, 256, GEMM_SMEM>>>(B, Wh + F * F, b1, A, NN);
    spmm2_final<<<(BQ + 15) / 16, 256>>>(A, b2, s, index, Wl, bl, out);
}

// round 17
// speedup vs baseline: 1.1381x; 1.0015x over previous
#include <cuda_runtime.h>
#include <cuda_fp16.h>
#include <cstdint>
#include <math.h>

#define NN      100000
#define NEDGE   1600000
#define F       128
#define BQ      8192
#define NSDIM   64
#define NC      16
#define SCAN_NB ((NN + 1023) / 1024)   // 98
#define ESPLIT  1152000                // ~72% of NEDGE on side stream

// ---------------- scratch (__device__ globals, allocation-free) ----------------
__device__ __half g_bufA[(size_t)NN * F];
__device__ __half g_bufB[(size_t)NN * F];
__device__ __half g_Wh[2][F * F];      // W1,W2 transposed [n][k], fp16

struct CsrScratch {              // zeroed with ONE memset per launch
    int cnt[NN];                 // edge histogram
    int iflag[NN];               // node is in index set
    int flag[NN];                // node is in C*
    int bsum[128];               // cnt scan block sums
    int lsum[128];               // flag scan block sums
    unsigned int ctr;            // grid barrier
    unsigned int pad[3];
};
__device__ CsrScratch g_cs;
__device__ int      g_ptr[NN + 1];
__device__ unsigned g_pmark[NN];   // ptr | (need << 31)
__device__ int      g_rank[NEDGE]; // within-row rank of each edge
__device__ int2     g_edge[NEDGE]; // packed (col, val-bits)
__device__ int      g_list[NN];    // compacted C* rows
__device__ int      g_nlist;       // |C*|

// fp16 GEMM smem: As2 [128 m][68] half2-as-u32, Ws2 [128 n][68] half2-as-u32
#define S2 68
#define GEMM_SMEM (2 * 128 * S2 * 4)   // 69632 B -> 2 blocks/SM

// ---------------- W transpose+convert ----------------
__global__ void wtrans_kernel(const float* __restrict__ W1, const float* __restrict__ W2)
{
    int idx = blockIdx.x * blockDim.x + threadIdx.x;   // 32768 total
    int w   = idx >> 14;
    int rem = idx & 16383;
    int k   = rem >> 7;
    int n   = rem & 127;
    const float* Wsrc = (w == 0) ? W1 : W2;
    g_Wh[w][n * F + k] = __float2half_rn(Wsrc[k * F + n]);
}

// ---------------- fp16 tensor-core GEMM ----------------
template <bool FUSE, bool LIST>
__global__ void gemm128_fp16(const void* __restrict__ Xv, const __half* __restrict__ Wh,
                             const float* __restrict__ bias, __half* __restrict__ C, int M)
{
    extern __shared__ unsigned int smu[];
    unsigned int* As2 = smu;             // [128][S2]
    unsigned int* Ws2 = smu + 128 * S2;  // [128][S2]

    const int tid  = threadIdx.x;
    const int wid  = tid >> 5;
    const int lane = tid & 31;
    const int gid  = lane >> 2;
    const int tig  = lane & 3;
    const int wm   = wid & 3;
    const int wn   = wid >> 2;
    const int m0   = blockIdx.x * 128;

    const int nl = LIST ? g_nlist : M;
    if (LIST && m0 >= nl) return;

    #pragma unroll
    for (int i = 0; i < 8; i++) {
        int idx = i * 256 + tid;
        int n = idx >> 4;
        int j = idx & 15;
        uint4 u = ((const uint4*)Wh)[idx];
        *(uint4*)(Ws2 + n * S2 + j * 4) = u;
    }

    if (FUSE) {
        const __half* Xh = (const __half*)Xv;
        #pragma unroll
        for (int i = 0; i < 8; i++) {
            int idx = i * 256 + tid;
            int m  = idx >> 4;
            int k8 = (idx & 15) << 3;
            int gm = m0 + m;
            bool valid = gm < nl;
            int src = (LIST && valid) ? g_list[gm] : gm;
            uint4 raw = make_uint4(0u, 0u, 0u, 0u);
            if (valid) raw = *(const uint4*)(Xh + (size_t)src * F + k8);
            const __half2* hp = (const __half2*)&raw;
            unsigned int o[4];
            #pragma unroll
            for (int j = 0; j < 4; j++) {
                float2 f = __half22float2(hp[j]);
                float2 bb = *(const float2*)(bias + k8 + j * 2);
                f.x = fmaxf(f.x + bb.x, 0.f);
                f.y = fmaxf(f.y + bb.y, 0.f);
                __half2 h = __floats2half2_rn(f.x, f.y);
                o[j] = *(unsigned int*)&h;
            }
            int base = m * S2 + (k8 >> 1);
            *(uint2*)(As2 + base)     = make_uint2(o[0], o[1]);
            *(uint2*)(As2 + base + 2) = make_uint2(o[2], o[3]);
        }
    } else {
        const float* Xf = (const float*)Xv;
        #pragma unroll
        for (int i = 0; i < 16; i++) {
            int idx = i * 256 + tid;
            int m  = idx >> 5;
            int k4 = (idx & 31) << 2;
            int gm = m0 + m;
            float4 v = make_float4(0.f, 0.f, 0.f, 0.f);
            if (gm < nl) v = *(const float4*)(Xf + (size_t)gm * F + k4);
            __half2 h0 = __floats2half2_rn(v.x, v.y);
            __half2 h1 = __floats2half2_rn(v.z, v.w);
            int base = m * S2 + (k4 >> 1);
            *(uint2*)(As2 + base) = make_uint2(*(unsigned int*)&h0, *(unsigned int*)&h1);
        }
    }
    __syncthreads();

    float acc[2][8][4];
    #pragma unroll
    for (int a = 0; a < 2; a++)
        #pragma unroll
        for (int b = 0; b < 8; b++)
            #pragma unroll
            for (int c = 0; c < 4; c++) acc[a][b][c] = 0.f;

    #pragma unroll
    for (int ks = 0; ks < 8; ks++) {
        const int k0h = ks * 8;
        unsigned int afr[2][4];
        #pragma unroll
        for (int mf = 0; mf < 2; mf++) {
            int rb = wm * 32 + mf * 16 + gid;
            afr[mf][0] = As2[rb * S2 + k0h + tig];
            afr[mf][1] = As2[(rb + 8) * S2 + k0h + tig];
            afr[mf][2] = As2[rb * S2 + k0h + 4 + tig];
            afr[mf][3] = As2[(rb + 8) * S2 + k0h + 4 + tig];
        }
        unsigned int bfr[8][2];
        #pragma unroll
        for (int nf = 0; nf < 8; nf++) {
            int nb = wn * 64 + nf * 8 + gid;
            bfr[nf][0] = Ws2[nb * S2 + k0h + tig];
            bfr[nf][1] = Ws2[nb * S2 + k0h + 4 + tig];
        }
        #pragma unroll
        for (int mf = 0; mf < 2; mf++)
            #pragma unroll
            for (int nf = 0; nf < 8; nf++) {
                asm volatile(
                    "mma.sync.aligned.m16n8k16.row.col.f32.f16.f16.f32 "
                    "{%0,%1,%2,%3}, {%4,%5,%6,%7}, {%8,%9}, {%0,%1,%2,%3};"
                    : "+f"(acc[mf][nf][0]), "+f"(acc[mf][nf][1]),
                      "+f"(acc[mf][nf][2]), "+f"(acc[mf][nf][3])
                    : "r"(afr[mf][0]), "r"(afr[mf][1]), "r"(afr[mf][2]), "r"(afr[mf][3]),
                      "r"(bfr[nf][0]), "r"(bfr[nf][1]));
            }
    }

    #pragma unroll
    for (int mf = 0; mf < 2; mf++) {
        int r0 = m0 + wm * 32 + mf * 16 + gid;
        bool v0 = r0 < nl;
        bool v1 = r0 + 8 < nl;
        int d0 = (LIST && v0) ? g_list[r0] : r0;
        int d1 = (LIST && v1) ? g_list[r0 + 8] : r0 + 8;
        #pragma unroll
        for (int nf = 0; nf < 8; nf++) {
            int ccol = wn * 64 + nf * 8 + tig * 2;
            if (v0)
                *(__half2*)(C + (size_t)d0 * F + ccol) =
                    __floats2half2_rn(acc[mf][nf][0], acc[mf][nf][1]);
            if (v1)
                *(__half2*)(C + (size_t)d1 * F + ccol) =
                    __floats2half2_rn(acc[mf][nf][2], acc[mf][nf][3]);
        }
    }
}

// ---------------- CSR + C* build kernels ----------------
__global__ void flagidx_kernel(const int* __restrict__ index)
{
    int b = blockIdx.x * blockDim.x + threadIdx.x;
    if (b < BQ) g_cs.iflag[index[b]] = 1;
}

// fused: histogram (returning per-edge rank) + C* mark
__global__ void histmark_kernel(const int* __restrict__ row, const int* __restrict__ col, int ne)
{
    int e = blockIdx.x * blockDim.x + threadIdx.x;
    if (e < ne) {
        int r = row[e];
        int rk = atomicAdd(&g_cs.cnt[r], 1);
        g_rank[e] = rk;
        if (g_cs.iflag[r]) g_cs.flag[col[e]] = 1;
    }
}

// fused dual scan (single grid barrier): cnt -> g_ptr/g_pmark, flag -> g_list/g_nlist
__global__ void scan_compact(int n, int ne)
{
    __shared__ int smc[256];
    __shared__ int smf[256];
    __shared__ int wsc[8];
    __shared__ int wsf[8];
    __shared__ int s_pc, s_pf;
    const int tid = threadIdx.x;
    const int bid = blockIdx.x;
    const int nb  = gridDim.x;
    const int base = bid * 1024 + tid * 4;

    int vc[4], vf[4], nd[4];
    #pragma unroll
    for (int i = 0; i < 4; i++) {
        bool ok = base + i < n;
        vc[i] = ok ? g_cs.cnt[base + i] : 0;
        vf[i] = ok ? g_cs.flag[base + i] : 0;
        nd[i] = ok ? (vf[i] | g_cs.iflag[base + i]) : 0;
    }
    int tc = vc[0] + vc[1] + vc[2] + vc[3];
    int tf = vf[0] + vf[1] + vf[2] + vf[3];
    smc[tid] = tc;
    smf[tid] = tf;
    __syncthreads();
    #pragma unroll
    for (int o = 1; o < 256; o <<= 1) {
        int t1 = (tid >= o) ? smc[tid - o] : 0;
        int t2 = (tid >= o) ? smf[tid - o] : 0;
        __syncthreads();
        smc[tid] += t1;
        smf[tid] += t2;
        __syncthreads();
    }

    if (tid == 0) {
        ((volatile int*)g_cs.bsum)[bid] = smc[255];
        ((volatile int*)g_cs.lsum)[bid] = smf[255];
        __threadfence();
        atomicAdd(&g_cs.ctr, 1u);
        while (((volatile unsigned int*)&g_cs.ctr)[0] < (unsigned)nb) {}
        __threadfence();
    }
    __syncthreads();

    int pc = (tid < bid) ? ((volatile int*)g_cs.bsum)[tid] : 0;
    int pf = (tid < bid) ? ((volatile int*)g_cs.lsum)[tid] : 0;
    #pragma unroll
    for (int o = 16; o; o >>= 1) {
        pc += __shfl_xor_sync(0xffffffffu, pc, o);
        pf += __shfl_xor_sync(0xffffffffu, pf, o);
    }
    if ((tid & 31) == 0) { wsc[tid >> 5] = pc; wsf[tid >> 5] = pf; }
    __syncthreads();
    if (tid < 8) {
        int q1 = wsc[tid], q2 = wsf[tid];
        #pragma unroll
        for (int o = 4; o; o >>= 1) {
            q1 += __shfl_xor_sync(0xffu, q1, o);
            q2 += __shfl_xor_sync(0xffu, q2, o);
        }
        if (tid == 0) { s_pc = q1; s_pf = q2; }
    }
    __syncthreads();

    int runc = s_pc + smc[tid] - tc;
    int runf = s_pf + smf[tid] - tf;
    #pragma unroll
    for (int i = 0; i < 4; i++) {
        if (base + i < n) {
            g_ptr[base + i]   = runc;
            g_pmark[base + i] = (unsigned)runc | (nd[i] ? 0x80000000u : 0u);
            if (vf[i]) g_list[runf] = base + i;
        }
        runc += vc[i];
        runf += vf[i];
    }
    if (bid == nb - 1 && tid == 255) {
        g_ptr[n] = ne;
        g_nlist = runf;
    }
}

// atomic-free scatter over an edge range [e0, e1)
__global__ void scatter_kernel(const int* __restrict__ row, const int* __restrict__ col,
                               const float* __restrict__ val, int e0, int e1)
{
    int e = e0 + blockIdx.x * blockDim.x + threadIdx.x;
    if (e < e1) {
        int r = row[e];
        unsigned pm = g_pmark[r];
        if (pm & 0x80000000u) {
            int p = (int)(pm & 0x7fffffffu) + g_rank[e];
            g_edge[p] = make_int2(col[e], __float_as_int(val[e]));
        }
    }
}

// ---------------- SPMM1 over compacted C* rows (int2 edges) ----------------
__global__ void __launch_bounds__(256, 6)
spmm_csr(const __half* __restrict__ H, __half* __restrict__ out)
{
    const int tid  = threadIdx.x;
    const int warp = tid >> 5;
    const int lane = tid & 31;
    const int half = lane >> 4;
    const int hl   = lane & 15;
    int li = blockIdx.x * 16 + warp * 2 + half;
    if (li >= g_nlist) return;
    int r = g_list[li];

    int e0 = g_ptr[r];
    int e1 = g_ptr[r + 1];

    float acc[8] = {0.f, 0.f, 0.f, 0.f, 0.f, 0.f, 0.f, 0.f};
    const size_t off = (size_t)hl * 8;

    int e = e0;
    for (; e + 4 <= e1; e += 4) {
        int2 d0 = g_edge[e],     d1 = g_edge[e + 1];
        int2 d2 = g_edge[e + 2], d3 = g_edge[e + 3];
        __half2 w0 = __float2half2_rn(__int_as_float(d0.y));
        __half2 w1 = __float2half2_rn(__int_as_float(d1.y));
        __half2 w2 = __float2half2_rn(__int_as_float(d2.y));
        __half2 w3 = __float2half2_rn(__int_as_float(d3.y));
        uint4 r0 = *(const uint4*)(H + (size_t)d0.x * F + off);
        uint4 r1 = *(const uint4*)(H + (size_t)d1.x * F + off);
        uint4 r2 = *(const uint4*)(H + (size_t)d2.x * F + off);
        uint4 r3 = *(const uint4*)(H + (size_t)d3.x * F + off);
        const __half2* h0 = (const __half2*)&r0;
        const __half2* h1 = (const __half2*)&r1;
        const __half2* h2 = (const __half2*)&r2;
        const __half2* h3 = (const __half2*)&r3;
        #pragma unroll
        for (int j = 0; j < 4; j++) {
            __half2 hacc = __hmul2(w0, h0[j]);
            hacc = __hfma2(w1, h1[j], hacc);
            hacc = __hfma2(w2, h2[j], hacc);
            hacc = __hfma2(w3, h3[j], hacc);
            float2 f = __half22float2(hacc);
            acc[j*2]   += f.x;
            acc[j*2+1] += f.y;
        }
    }
    for (; e < e1; e++) {
        int2 d = g_edge[e];
        float v = __int_as_float(d.y);
        uint4 rr = *(const uint4*)(H + (size_t)d.x * F + off);
        const __half2* hh = (const __half2*)&rr;
        #pragma unroll
        for (int j = 0; j < 4; j++) {
            float2 f = __half22float2(hh[j]);
            acc[j*2]   += v * f.x;
            acc[j*2+1] += v * f.y;
        }
    }
    uint4 o;
    __half2* op = (__half2*)&o;
    #pragma unroll
    for (int j = 0; j < 4; j++)
        op[j] = __floats2half2_rn(acc[j*2], acc[j*2+1]);
    *(uint4*)(out + (size_t)r * F + off) = o;
}

// ---------------- fused: row-restricted SPMM2 + linear + log_softmax ----------------
__global__ void __launch_bounds__(256, 6)
spmm2_final(const __half* __restrict__ H2, const float* __restrict__ b2,
            const float* __restrict__ s, const int* __restrict__ index,
            const float* __restrict__ Wl, const float* __restrict__ bl,
            float* __restrict__ out)
{
    __shared__ float Wls[(F + NSDIM) * NC];
    __shared__ float bls[NC];
    __shared__ float sin[16][F + NSDIM];

    for (int i = threadIdx.x; i < (F + NSDIM) * NC; i += blockDim.x) Wls[i] = Wl[i];
    if (threadIdx.x < NC) bls[threadIdx.x] = bl[threadIdx.x];
    __syncthreads();

    const int tid  = threadIdx.x;
    const int warp = tid >> 5;
    const int lane = tid & 31;
    const int half = lane >> 4;
    const int hl   = lane & 15;
    const int sidx = warp * 2 + half;
    int b = blockIdx.x * 16 + sidx;
    if (b >= BQ) return;

    int r = __ldg(index + b);
    int e0 = g_ptr[r];
    int e1 = g_ptr[r + 1];

    float acc[8] = {0.f, 0.f, 0.f, 0.f, 0.f, 0.f, 0.f, 0.f};
    const size_t off = (size_t)hl * 8;

    int e = e0;
    for (; e + 4 <= e1; e += 4) {
        int2 d0 = g_edge[e],     d1 = g_edge[e + 1];
        int2 d2 = g_edge[e + 2], d3 = g_edge[e + 3];
        __half2 w0 = __float2half2_rn(__int_as_float(d0.y));
        __half2 w1 = __float2half2_rn(__int_as_float(d1.y));
        __half2 w2 = __float2half2_rn(__int_as_float(d2.y));
        __half2 w3 = __float2half2_rn(__int_as_float(d3.y));
        uint4 r0 = *(const uint4*)(H2 + (size_t)d0.x * F + off);
        uint4 r1 = *(const uint4*)(H2 + (size_t)d1.x * F + off);
        uint4 r2 = *(const uint4*)(H2 + (size_t)d2.x * F + off);
        uint4 r3 = *(const uint4*)(H2 + (size_t)d3.x * F + off);
        const __half2* h0 = (const __half2*)&r0;
        const __half2* h1 = (const __half2*)&r1;
        const __half2* h2 = (const __half2*)&r2;
        const __half2* h3 = (const __half2*)&r3;
        #pragma unroll
        for (int j = 0; j < 4; j++) {
            __half2 hacc = __hmul2(w0, h0[j]);
            hacc = __hfma2(w1, h1[j], hacc);
            hacc = __hfma2(w2, h2[j], hacc);
            hacc = __hfma2(w3, h3[j], hacc);
            float2 f = __half22float2(hacc);
            acc[j*2]   += f.x;
            acc[j*2+1] += f.y;
        }
    }
    for (; e < e1; e++) {
        int2 d = g_edge[e];
        float v = __int_as_float(d.y);
        uint4 rr = *(const uint4*)(H2 + (size_t)d.x * F + off);
        const __half2* hh = (const __half2*)&rr;
        #pragma unroll
        for (int j = 0; j < 4; j++) {
            float2 f = __half22float2(hh[j]);
            acc[j*2]   += v * f.x;
            acc[j*2+1] += v * f.y;
        }
    }

    #pragma unroll
    for (int j = 0; j < 8; j++)
        sin[sidx][hl * 8 + j] = acc[j] + b2[hl * 8 + j];
    #pragma unroll
    for (int j = 0; j < 4; j++)
        sin[sidx][F + hl * 4 + j] = s[(size_t)b * NSDIM + hl * 4 + j];
    __syncwarp();

    float z = bls[hl];
    #pragma unroll 4
    for (int k = 0; k < F + NSDIM; k++)
        z += sin[sidx][k] * Wls[k * NC + hl];

    float m = z;
    #pragma unroll
    for (int o = 8; o > 0; o >>= 1)
        m = fmaxf(m, __shfl_xor_sync(0xffffffffu, m, o, 16));
    float ex = expf(z - m);
    float sum = ex;
    #pragma unroll
    for (int o = 8; o > 0; o >>= 1)
        sum += __shfl_xor_sync(0xffffffffu, sum, o, 16);
    out[(size_t)b * NC + hl] = z - m - logf(sum);
}

// ---------------- launch ----------------
extern "C" void kernel_launch(void* const* d_in, const int* in_sizes, int n_in,
                              void* d_out, int out_size)
{
    const float* s    = (const float*)d_in[0];
    const float* x    = (const float*)d_in[1];
    const int*   row  = (const int*)  d_in[2];
    const int*   col  = (const int*)  d_in[3];
    const float* val  = (const float*)d_in[4];
    const int*   index= (const int*)  d_in[5];
    const float* W1   = (const float*)d_in[6];
    const float* b1   = (const float*)d_in[7];
    const float* W2   = (const float*)d_in[8];
    const float* b2   = (const float*)d_in[9];
    const float* Wl   = (const float*)d_in[10];
    const float* bl   = (const float*)d_in[11];
    float* out = (float*)d_out;

    __half *A, *B, *Wh;
    void *csp;
    cudaGetSymbolAddress((void**)&A, g_bufA);
    cudaGetSymbolAddress((void**)&B, g_bufB);
    cudaGetSymbolAddress((void**)&Wh, g_Wh);
    cudaGetSymbolAddress(&csp, g_cs);

    static cudaStream_t side = nullptr;
    static cudaEvent_t evFork = nullptr, evScan = nullptr, evSide = nullptr;
    if (side == nullptr) {
        cudaStreamCreateWithFlags(&side, cudaStreamNonBlocking);
        cudaEventCreateWithFlags(&evFork, cudaEventDisableTiming);
        cudaEventCreateWithFlags(&evScan, cudaEventDisableTiming);
        cudaEventCreateWithFlags(&evSide, cudaEventDisableTiming);
        cudaFuncSetAttribute((const void*)gemm128_fp16<false, false>, cudaFuncAttributeMaxDynamicSharedMemorySize, GEMM_SMEM);
        cudaFuncSetAttribute((const void*)gemm128_fp16<true, true>,   cudaFuncAttributeMaxDynamicSharedMemorySize, GEMM_SMEM);
    }

    const int gemm_grid  = (NN + 127) / 128;           // 782
    const int edge_grid  = (NEDGE + 255) / 256;        // 6250

    // fork: CSR + C* build on side stream; scatter split [0,ESPLIT) on side
    cudaEventRecord(evFork, 0);
    cudaStreamWaitEvent(side, evFork, 0);
    cudaMemsetAsync(csp, 0, sizeof(CsrScratch), side);
    flagidx_kernel<<<(BQ + 255) / 256, 256, 0, side>>>(index);
    histmark_kernel<<<edge_grid, 256, 0, side>>>(row, col, NEDGE);
    scan_compact<<<SCAN_NB, 256, 0, side>>>(NN, NEDGE);
    cudaEventRecord(evScan, side);
    scatter_kernel<<<(ESPLIT + 255) / 256, 256, 0, side>>>(row, col, val, 0, ESPLIT);
    cudaEventRecord(evSide, side);

    // main stream: W transpose, GEMM1 (concurrent with side build),
    // then the tail of the scatter [ESPLIT, NEDGE) once scan is done
    wtrans_kernel<<<128, 256>>>(W1, W2);
    gemm128_fp16<false, false><<<gemm_grid, 256, GEMM_SMEM>>>(x, Wh, nullptr, A, NN);
    cudaStreamWaitEvent(0, evScan, 0);
    scatter_kernel<<<(NEDGE - ESPLIT + 255) / 256, 256>>>(row, col, val, ESPLIT, NEDGE);

    // join, then the dependent chain (restricted to C*)
    cudaStreamWaitEvent(0, evSide, 0);
    spmm_csr<<<(NN + 15) / 16, 256>>>(A, B);
    gemm128_fp16<true, true><<<gemm_grid, 256, GEMM_SMEM>>>(B, Wh + F * F, b1, A, NN);
    spmm2_final<<<(BQ + 15) / 16, 256>>>(A, b2, s, index, Wl, bl, out);
}